// round 5
// baseline (speedup 1.0000x reference)
#include <cuda_runtime.h>
#include <cstdint>

// ---------------- problem constants ----------------
#define Wd   384
#define Hd   384
#define Cd   256
#define HWd  (Wd * Hd)          // 147456
#define NOBJ 16
#define NP   128
#define NN   2048
#define NKP  2048               // N_OBJ * N_P key points
#define NPTS (NKP + NOBJ * NN)  // 34816 total sampled points
#define NTILES 16               // 2048 / 128 n-tiles per object

// ---------------- device scratch (static: no allocations allowed) ----------------
__device__ float g_imgT[(size_t)HWd * Cd];      // [s][c]  (151 MB, transposed image)
__device__ float g_F[(size_t)NPTS * Cd];        // [pt][c] sampled features (35.7 MB)
__device__ int   g_cnt [NOBJ * NP * NTILES];    // per (o,p,ntile) partials
__device__ float g_dsum[NOBJ * NP * NTILES];
__device__ float g_dmin[NOBJ * NP * NTILES];

// =================================================================
// Kernel 1: transpose feats [C,H,W] -> g_imgT [H*W, C]
// 32x32 tile, float4 on both global sides, conflict-free smem.
// =================================================================
__global__ void transpose_kernel(const float* __restrict__ in) {
    __shared__ float tile[32][33];
    const int bs = blockIdx.x * 32;     // s base (pixel index)
    const int bc = blockIdx.y * 32;     // c base
    const int tx = threadIdx.x;         // 0..7  : vec4 along s (load) / along c (store)
    const int ty = threadIdx.y;         // 0..31 : c (load) / s (store)

    const float4 v = *(const float4*)(in + (size_t)(bc + ty) * HWd + bs + tx * 4);
    tile[ty][tx * 4 + 0] = v.x;
    tile[ty][tx * 4 + 1] = v.y;
    tile[ty][tx * 4 + 2] = v.z;
    tile[ty][tx * 4 + 3] = v.w;
    __syncthreads();

    float4 w;
    w.x = tile[tx * 4 + 0][ty];
    w.y = tile[tx * 4 + 1][ty];
    w.z = tile[tx * 4 + 2][ty];
    w.w = tile[tx * 4 + 3][ty];
    *(float4*)(g_imgT + (size_t)(bs + ty) * Cd + bc + tx * 4) = w;
}

// =================================================================
// Kernel 2: bilinear grid-sample all 34816 points from g_imgT.
// Points 0..2047 come from key_points, 2048.. from point_set_2.
// Block = 4 points x 64 channel-vec4 lanes. All loads/stores are
// fully coalesced (1 KB contiguous per tap per point).
// =================================================================
__global__ void sample_kernel(const float* __restrict__ kp,
                              const float* __restrict__ ps2) {
    const int tx = threadIdx.x;                       // 0..63  channel quad
    const int pt = blockIdx.x * 4 + threadIdx.y;      // 0..34815

    const float* src = (pt < NKP) ? (kp + (size_t)pt * 2)
                                  : (ps2 + (size_t)(pt - NKP) * 2);
    const float px = src[0];
    const float py = src[1];

    // exact reference math (grid_sample, align_corners=False)
    const float gx = 2.0f * (px * (1.0f / 384.0f)) - 1.0f;
    const float gy = 2.0f * (py * (1.0f / 384.0f)) - 1.0f;
    const float x  = ((gx + 1.0f) * 384.0f - 1.0f) * 0.5f;
    const float y  = ((gy + 1.0f) * 384.0f - 1.0f) * 0.5f;

    const float x0f = floorf(x), y0f = floorf(y);
    const float wx1 = x - x0f,   wy1 = y - y0f;
    const float wx0 = 1.0f - wx1, wy0 = 1.0f - wy1;
    const int x0 = (int)x0f, y0 = (int)y0f;
    const int x1 = x0 + 1,   y1 = y0 + 1;

    const float vx0 = (x0 >= 0 && x0 < Wd) ? 1.0f : 0.0f;
    const float vx1 = (x1 >= 0 && x1 < Wd) ? 1.0f : 0.0f;
    const float vy0 = (y0 >= 0 && y0 < Hd) ? 1.0f : 0.0f;
    const float vy1 = (y1 >= 0 && y1 < Hd) ? 1.0f : 0.0f;

    const float w00 = wx0 * wy0 * vx0 * vy0;
    const float w10 = wx1 * wy0 * vx1 * vy0;
    const float w01 = wx0 * wy1 * vx0 * vy1;
    const float w11 = wx1 * wy1 * vx1 * vy1;

    const int xc0 = min(max(x0, 0), Wd - 1);
    const int xc1 = min(max(x1, 0), Wd - 1);
    const int yc0 = min(max(y0, 0), Hd - 1);
    const int yc1 = min(max(y1, 0), Hd - 1);

    const size_t coff = (size_t)tx * 4;
    const float4 t00 = *(const float4*)(g_imgT + ((size_t)(yc0 * Wd + xc0)) * Cd + coff);
    const float4 t10 = *(const float4*)(g_imgT + ((size_t)(yc0 * Wd + xc1)) * Cd + coff);
    const float4 t01 = *(const float4*)(g_imgT + ((size_t)(yc1 * Wd + xc0)) * Cd + coff);
    const float4 t11 = *(const float4*)(g_imgT + ((size_t)(yc1 * Wd + xc1)) * Cd + coff);

    float4 acc;
    acc.x = w00 * t00.x + w10 * t10.x + w01 * t01.x + w11 * t11.x;
    acc.y = w00 * t00.y + w10 * t10.y + w01 * t01.y + w11 * t11.y;
    acc.z = w00 * t00.z + w10 * t10.z + w01 * t01.z + w11 * t11.z;
    acc.w = w00 * t00.w + w10 * t10.w + w01 * t01.w + w11 * t11.w;

    *(float4*)(g_F + (size_t)pt * Cd + coff) = acc;
}

// =================================================================
// Kernel 3: fused GEMM(sign) + distance + masked reduction.
// Block = (o, n-tile): computes dot(f1[o,p], f2[o,n]) for a
// 128p x 128n tile with K=256, using packed fp32x2 FFMA2 (full-rate
// fp32 on sm_103a; plain 3-reg FFMA is half rate).  Epilogue masks
// on dot>=0, accumulates (cnt, sum d, min d) per p over the tile,
// reduces across the 16 tx lanes via shfl, writes partials.
// =================================================================
#define FMA2(d, a, b) \
    asm("fma.rn.f32x2 %0, %1, %2, %3;" : "=l"(d) : "l"(a), "l"(b), "l"(d))

__global__ __launch_bounds__(256)
void gemm_mask_kernel(const float* __restrict__ ps1,
                      const float* __restrict__ ps2) {
    __shared__ unsigned long long As2[8][130];  // A values duplicated into f32x2 pairs
    __shared__ float Bs[8][132];
    __shared__ float s1x[128], s1y[128], s2x[128], s2y[128];

    const int o  = blockIdx.y;
    const int nt = blockIdx.x;
    const int tid = threadIdx.x;
    const int tx = tid & 15;        // n micro-tile
    const int ty = tid >> 4;        // p micro-tile

    const float* A = g_F + (size_t)(o * 128) * Cd;                       // f1 rows
    const float* B = g_F + (size_t)(NKP + o * NN + nt * 128) * Cd;       // f2 rows

    if (tid < 128) {
        const size_t i1 = ((size_t)o * NP + tid) * 2;
        s1x[tid] = ps1[i1];
        s1y[tid] = ps1[i1 + 1];
        const size_t i2 = ((size_t)o * NN + nt * 128 + tid) * 2;
        s2x[tid] = ps2[i2];
        s2y[tid] = ps2[i2 + 1];
    }

    unsigned long long acc[8][4];
    #pragma unroll
    for (int i = 0; i < 8; i++)
        #pragma unroll
        for (int j = 0; j < 4; j++) acc[i][j] = 0ull;

    const int lrow = tid >> 1;            // 0..127
    const int lk   = (tid & 1) * 4;       // 0 or 4
    const float* Ap = A + (size_t)lrow * Cd + lk;
    const float* Bp = B + (size_t)lrow * Cd + lk;

    for (int k0 = 0; k0 < Cd; k0 += 8) {
        const float4 av = *(const float4*)(Ap + k0);
        const float4 bv = *(const float4*)(Bp + k0);
        __syncthreads();   // previous iteration's readers done
        unsigned long long d0, d1, d2, d3;
        asm("mov.b64 %0, {%1, %1};" : "=l"(d0) : "r"(__float_as_uint(av.x)));
        asm("mov.b64 %0, {%1, %1};" : "=l"(d1) : "r"(__float_as_uint(av.y)));
        asm("mov.b64 %0, {%1, %1};" : "=l"(d2) : "r"(__float_as_uint(av.z)));
        asm("mov.b64 %0, {%1, %1};" : "=l"(d3) : "r"(__float_as_uint(av.w)));
        As2[lk + 0][lrow] = d0;
        As2[lk + 1][lrow] = d1;
        As2[lk + 2][lrow] = d2;
        As2[lk + 3][lrow] = d3;
        Bs[lk + 0][lrow] = bv.x;
        Bs[lk + 1][lrow] = bv.y;
        Bs[lk + 2][lrow] = bv.z;
        Bs[lk + 3][lrow] = bv.w;
        __syncthreads();

        #pragma unroll
        for (int kk = 0; kk < 8; kk++) {
            const ulonglong2* ap = (const ulonglong2*)&As2[kk][ty * 8];
            const ulonglong2 a01 = ap[0], a23 = ap[1], a45 = ap[2], a67 = ap[3];
            const ulonglong2* bp = (const ulonglong2*)&Bs[kk][tx * 8];
            const ulonglong2 b01 = bp[0], b23 = bp[1];
            const unsigned long long a[8] = {a01.x, a01.y, a23.x, a23.y,
                                             a45.x, a45.y, a67.x, a67.y};
            const unsigned long long b[4] = {b01.x, b01.y, b23.x, b23.y};
            #pragma unroll
            for (int i = 0; i < 8; i++)
                #pragma unroll
                for (int j = 0; j < 4; j++)
                    FMA2(acc[i][j], a[i], b[j]);
        }
    }

    // ---- epilogue: mask, distances, per-p reduction ----
    #pragma unroll
    for (int i = 0; i < 8; i++) {
        const int p = ty * 8 + i;
        const float px = s1x[p], py = s1y[p];
        int   cnt  = 0;
        float dsum = 0.0f;
        float dmin = 3.402823466e38f;
        #pragma unroll
        for (int j = 0; j < 4; j++) {
            unsigned lo_u, hi_u;
            asm("mov.b64 {%0, %1}, %2;" : "=r"(lo_u), "=r"(hi_u) : "l"(acc[i][j]));
            const float dlo = __uint_as_float(lo_u);
            const float dhi = __uint_as_float(hi_u);
            const int n0 = tx * 8 + 2 * j;
            if (dlo >= 0.0f) {
                const float dx = px - s2x[n0], dy = py - s2y[n0];
                const float d = sqrtf(dx * dx + dy * dy);
                cnt++; dsum += d; dmin = fminf(dmin, d);
            }
            if (dhi >= 0.0f) {
                const float dx = px - s2x[n0 + 1], dy = py - s2y[n0 + 1];
                const float d = sqrtf(dx * dx + dy * dy);
                cnt++; dsum += d; dmin = fminf(dmin, d);
            }
        }
        // reduce across the 16 tx lanes (lane bits 0..3)
        #pragma unroll
        for (int off = 1; off < 16; off <<= 1) {
            cnt  += __shfl_xor_sync(0xffffffffu, cnt,  off);
            dsum += __shfl_xor_sync(0xffffffffu, dsum, off);
            dmin  = fminf(dmin, __shfl_xor_sync(0xffffffffu, dmin, off));
        }
        if (tx == 0) {
            const int idx = (o * NP + p) * NTILES + nt;
            g_cnt[idx]  = cnt;
            g_dsum[idx] = dsum;
            g_dmin[idx] = dmin;
        }
    }
}

// =================================================================
// Kernel 4: combine tile partials -> chamfer costs -> scalar loss.
// =================================================================
__global__ void final_kernel(const float* __restrict__ ps2,
                             float* __restrict__ out) {
    __shared__ float sm_m[NOBJ];
    __shared__ float red[512];
    const int tid  = threadIdx.x;
    const int w    = tid >> 5;
    const int lane = tid & 31;

    if (w < NOBJ) {  // m[o] = (sum(point_set_2[o]) >= 0)
        float s = 0.0f;
        const float* p = ps2 + (size_t)w * (NN * 2);
        for (int i = lane; i < NN * 2; i += 32) s += p[i];
        #pragma unroll
        for (int off = 16; off; off >>= 1) s += __shfl_xor_sync(0xffffffffu, s, off);
        if (lane == 0) sm_m[w] = (s >= 0.0f) ? 1.0f : 0.0f;
    }
    __syncthreads();

    float local = 0.0f;
    for (int cell = tid; cell < NOBJ * NP; cell += 512) {
        const int idx0 = cell * NTILES;
        int   cnt  = 0;
        float dsum = 0.0f;
        float dmin = 3.402823466e38f;
        #pragma unroll
        for (int t = 0; t < NTILES; t++) {
            cnt  += g_cnt[idx0 + t];
            dsum += g_dsum[idx0 + t];
            dmin  = fminf(dmin, g_dmin[idx0 + t]);
        }
        if (cnt > 0)
            local += 0.5f * (dmin + dsum / (float)cnt) * sm_m[cell >> 7];
    }
    red[tid] = local;
    __syncthreads();
    for (int s = 256; s > 0; s >>= 1) {
        if (tid < s) red[tid] += red[tid + s];
        __syncthreads();
    }
    if (tid == 0) out[0] = red[0] * (1.0f / (float)(NOBJ * NP));
}

// =================================================================
// kernel_launch: 4 launches, graph-capturable, no allocations.
// =================================================================
extern "C" void kernel_launch(void* const* d_in, const int* in_sizes, int n_in,
                              void* d_out, int out_size) {
    // Identify inputs by element count (robust to index assumptions):
    //   point_set_1: 16*128*2  = 4096   (first 4096-sized input)
    //   point_set_2: 16*2048*2 = 65536
    //   feats:       256*384*384 = 37748736
    //   key_points:  2048*2    = 4096   (second 4096-sized input)
    const float* ps1   = nullptr;
    const float* ps2   = nullptr;
    const float* feats = nullptr;
    const float* kp    = nullptr;
    for (int i = 0; i < n_in; i++) {
        if (in_sizes[i] == 37748736)      feats = (const float*)d_in[i];
        else if (in_sizes[i] == 65536)    ps2   = (const float*)d_in[i];
        else if (in_sizes[i] == 4096) {
            if (!ps1) ps1 = (const float*)d_in[i];
            else      kp  = (const float*)d_in[i];
        }
    }
    float* out = (float*)d_out;

    transpose_kernel<<<dim3(HWd / 32, Cd / 32), dim3(8, 32)>>>(feats);
    sample_kernel<<<NPTS / 4, dim3(64, 4)>>>(kp, ps2);
    gemm_mask_kernel<<<dim3(NTILES, NOBJ), 256>>>(ps1, ps2);
    final_kernel<<<1, 512>>>(ps2, out);
}

// round 6
// speedup vs baseline: 1.1114x; 1.1114x over previous
#include <cuda_runtime.h>
#include <cstdint>

// ---------------- problem constants ----------------
#define Wd   384
#define Hd   384
#define Cd   256
#define HWd  (Wd * Hd)          // 147456
#define NOBJ 16
#define NP   128
#define NN   2048
#define NKP  2048               // N_OBJ * N_P key points
#define NPTS (NKP + NOBJ * NN)  // 34816 total sampled points
#define NTILES 16               // 2048 / 128 n-tiles per object

// ---------------- device scratch (static: no allocations allowed) ----------------
__device__ float g_imgT[(size_t)HWd * Cd];      // [s][c]  (151 MB, transposed image)
__device__ float g_F[(size_t)NPTS * Cd];        // [pt][c] sampled features (35.7 MB)
__device__ int   g_cnt [NOBJ * NP * NTILES];    // per (o,p,ntile) partials
__device__ float g_dsum[NOBJ * NP * NTILES];
__device__ float g_dmin[NOBJ * NP * NTILES];
__device__ float g_m[NOBJ];                     // per-object validity mask

// =================================================================
// Kernel 0: m[o] = (sum(point_set_2[o]) >= 0). 16 blocks, float4.
// Off the critical path (launched first, independent of everything).
// =================================================================
__global__ __launch_bounds__(256)
void m_kernel(const float* __restrict__ ps2) {
    __shared__ float red[8];
    const int o   = blockIdx.x;
    const int tid = threadIdx.x;
    const float4* p = (const float4*)(ps2 + (size_t)o * (NN * 2));
    float s = 0.0f;
    #pragma unroll
    for (int i = 0; i < 16; i++) {          // 4096 float4 / 256 threads
        const float4 v = p[tid + i * 256];
        s += v.x + v.y + v.z + v.w;
    }
    #pragma unroll
    for (int off = 16; off; off >>= 1) s += __shfl_xor_sync(0xffffffffu, s, off);
    if ((tid & 31) == 0) red[tid >> 5] = s;
    __syncthreads();
    if (tid == 0) {
        float t = 0.0f;
        #pragma unroll
        for (int w = 0; w < 8; w++) t += red[w];
        g_m[o] = (t >= 0.0f) ? 1.0f : 0.0f;
    }
}

// =================================================================
// Kernel 1: transpose feats [C,H,W] -> g_imgT [H*W, C]
// 32x32 tile, float4 on both global sides, conflict-free smem.
// =================================================================
__global__ void transpose_kernel(const float* __restrict__ in) {
    __shared__ float tile[32][33];
    const int bs = blockIdx.x * 32;     // s base (pixel index)
    const int bc = blockIdx.y * 32;     // c base
    const int tx = threadIdx.x;         // 0..7  : vec4 along s (load) / along c (store)
    const int ty = threadIdx.y;         // 0..31 : c (load) / s (store)

    const float4 v = *(const float4*)(in + (size_t)(bc + ty) * HWd + bs + tx * 4);
    tile[ty][tx * 4 + 0] = v.x;
    tile[ty][tx * 4 + 1] = v.y;
    tile[ty][tx * 4 + 2] = v.z;
    tile[ty][tx * 4 + 3] = v.w;
    __syncthreads();

    float4 w;
    w.x = tile[tx * 4 + 0][ty];
    w.y = tile[tx * 4 + 1][ty];
    w.z = tile[tx * 4 + 2][ty];
    w.w = tile[tx * 4 + 3][ty];
    *(float4*)(g_imgT + (size_t)(bs + ty) * Cd + bc + tx * 4) = w;
}

// =================================================================
// Kernel 2: bilinear grid-sample all 34816 points from g_imgT.
// Points 0..2047 come from key_points, 2048.. from point_set_2.
// Block = 4 points x 64 channel-vec4 lanes. All loads/stores are
// fully coalesced (1 KB contiguous per tap per point).
// =================================================================
__global__ void sample_kernel(const float* __restrict__ kp,
                              const float* __restrict__ ps2) {
    const int tx = threadIdx.x;                       // 0..63  channel quad
    const int pt = blockIdx.x * 4 + threadIdx.y;      // 0..34815

    const float* src = (pt < NKP) ? (kp + (size_t)pt * 2)
                                  : (ps2 + (size_t)(pt - NKP) * 2);
    const float px = src[0];
    const float py = src[1];

    // exact reference math (grid_sample, align_corners=False)
    const float gx = 2.0f * (px * (1.0f / 384.0f)) - 1.0f;
    const float gy = 2.0f * (py * (1.0f / 384.0f)) - 1.0f;
    const float x  = ((gx + 1.0f) * 384.0f - 1.0f) * 0.5f;
    const float y  = ((gy + 1.0f) * 384.0f - 1.0f) * 0.5f;

    const float x0f = floorf(x), y0f = floorf(y);
    const float wx1 = x - x0f,   wy1 = y - y0f;
    const float wx0 = 1.0f - wx1, wy0 = 1.0f - wy1;
    const int x0 = (int)x0f, y0 = (int)y0f;
    const int x1 = x0 + 1,   y1 = y0 + 1;

    const float vx0 = (x0 >= 0 && x0 < Wd) ? 1.0f : 0.0f;
    const float vx1 = (x1 >= 0 && x1 < Wd) ? 1.0f : 0.0f;
    const float vy0 = (y0 >= 0 && y0 < Hd) ? 1.0f : 0.0f;
    const float vy1 = (y1 >= 0 && y1 < Hd) ? 1.0f : 0.0f;

    const float w00 = wx0 * wy0 * vx0 * vy0;
    const float w10 = wx1 * wy0 * vx1 * vy0;
    const float w01 = wx0 * wy1 * vx0 * vy1;
    const float w11 = wx1 * wy1 * vx1 * vy1;

    const int xc0 = min(max(x0, 0), Wd - 1);
    const int xc1 = min(max(x1, 0), Wd - 1);
    const int yc0 = min(max(y0, 0), Hd - 1);
    const int yc1 = min(max(y1, 0), Hd - 1);

    const size_t coff = (size_t)tx * 4;
    const float4 t00 = *(const float4*)(g_imgT + ((size_t)(yc0 * Wd + xc0)) * Cd + coff);
    const float4 t10 = *(const float4*)(g_imgT + ((size_t)(yc0 * Wd + xc1)) * Cd + coff);
    const float4 t01 = *(const float4*)(g_imgT + ((size_t)(yc1 * Wd + xc0)) * Cd + coff);
    const float4 t11 = *(const float4*)(g_imgT + ((size_t)(yc1 * Wd + xc1)) * Cd + coff);

    float4 acc;
    acc.x = w00 * t00.x + w10 * t10.x + w01 * t01.x + w11 * t11.x;
    acc.y = w00 * t00.y + w10 * t10.y + w01 * t01.y + w11 * t11.y;
    acc.z = w00 * t00.z + w10 * t10.z + w01 * t01.z + w11 * t11.z;
    acc.w = w00 * t00.w + w10 * t10.w + w01 * t01.w + w11 * t11.w;

    *(float4*)(g_F + (size_t)pt * Cd + coff) = acc;
}

// =================================================================
// Kernel 3: fused GEMM(sign) + distance + masked reduction.
// Block = (o, n-tile): computes dot(f1[o,p], f2[o,n]) for a
// 128p x 128n tile with K=256, using packed fp32x2 FFMA2 (full-rate
// fp32 on sm_103a; plain 3-reg FFMA is half rate).  Epilogue masks
// on dot>=0, accumulates (cnt, sum d, min d) per p over the tile,
// reduces across the 16 tx lanes via shfl, writes partials.
// =================================================================
#define FMA2(d, a, b) \
    asm("fma.rn.f32x2 %0, %1, %2, %3;" : "=l"(d) : "l"(a), "l"(b), "l"(d))

__global__ __launch_bounds__(256)
void gemm_mask_kernel(const float* __restrict__ ps1,
                      const float* __restrict__ ps2) {
    __shared__ unsigned long long As2[8][130];  // A values duplicated into f32x2 pairs
    __shared__ float Bs[8][132];
    __shared__ float s1x[128], s1y[128], s2x[128], s2y[128];

    const int o  = blockIdx.y;
    const int nt = blockIdx.x;
    const int tid = threadIdx.x;
    const int tx = tid & 15;        // n micro-tile
    const int ty = tid >> 4;        // p micro-tile

    const float* A = g_F + (size_t)(o * 128) * Cd;                       // f1 rows
    const float* B = g_F + (size_t)(NKP + o * NN + nt * 128) * Cd;       // f2 rows

    if (tid < 128) {
        const size_t i1 = ((size_t)o * NP + tid) * 2;
        s1x[tid] = ps1[i1];
        s1y[tid] = ps1[i1 + 1];
        const size_t i2 = ((size_t)o * NN + nt * 128 + tid) * 2;
        s2x[tid] = ps2[i2];
        s2y[tid] = ps2[i2 + 1];
    }

    unsigned long long acc[8][4];
    #pragma unroll
    for (int i = 0; i < 8; i++)
        #pragma unroll
        for (int j = 0; j < 4; j++) acc[i][j] = 0ull;

    const int lrow = tid >> 1;            // 0..127
    const int lk   = (tid & 1) * 4;       // 0 or 4
    const float* Ap = A + (size_t)lrow * Cd + lk;
    const float* Bp = B + (size_t)lrow * Cd + lk;

    for (int k0 = 0; k0 < Cd; k0 += 8) {
        const float4 av = *(const float4*)(Ap + k0);
        const float4 bv = *(const float4*)(Bp + k0);
        __syncthreads();   // previous iteration's readers done
        unsigned long long d0, d1, d2, d3;
        asm("mov.b64 %0, {%1, %1};" : "=l"(d0) : "r"(__float_as_uint(av.x)));
        asm("mov.b64 %0, {%1, %1};" : "=l"(d1) : "r"(__float_as_uint(av.y)));
        asm("mov.b64 %0, {%1, %1};" : "=l"(d2) : "r"(__float_as_uint(av.z)));
        asm("mov.b64 %0, {%1, %1};" : "=l"(d3) : "r"(__float_as_uint(av.w)));
        As2[lk + 0][lrow] = d0;
        As2[lk + 1][lrow] = d1;
        As2[lk + 2][lrow] = d2;
        As2[lk + 3][lrow] = d3;
        Bs[lk + 0][lrow] = bv.x;
        Bs[lk + 1][lrow] = bv.y;
        Bs[lk + 2][lrow] = bv.z;
        Bs[lk + 3][lrow] = bv.w;
        __syncthreads();

        #pragma unroll
        for (int kk = 0; kk < 8; kk++) {
            const ulonglong2* ap = (const ulonglong2*)&As2[kk][ty * 8];
            const ulonglong2 a01 = ap[0], a23 = ap[1], a45 = ap[2], a67 = ap[3];
            const ulonglong2* bp = (const ulonglong2*)&Bs[kk][tx * 8];
            const ulonglong2 b01 = bp[0], b23 = bp[1];
            const unsigned long long a[8] = {a01.x, a01.y, a23.x, a23.y,
                                             a45.x, a45.y, a67.x, a67.y};
            const unsigned long long b[4] = {b01.x, b01.y, b23.x, b23.y};
            #pragma unroll
            for (int i = 0; i < 8; i++)
                #pragma unroll
                for (int j = 0; j < 4; j++)
                    FMA2(acc[i][j], a[i], b[j]);
        }
    }

    // ---- epilogue: mask, distances, per-p reduction ----
    #pragma unroll
    for (int i = 0; i < 8; i++) {
        const int p = ty * 8 + i;
        const float px = s1x[p], py = s1y[p];
        int   cnt  = 0;
        float dsum = 0.0f;
        float dmin = 3.402823466e38f;
        #pragma unroll
        for (int j = 0; j < 4; j++) {
            unsigned lo_u, hi_u;
            asm("mov.b64 {%0, %1}, %2;" : "=r"(lo_u), "=r"(hi_u) : "l"(acc[i][j]));
            const float dlo = __uint_as_float(lo_u);
            const float dhi = __uint_as_float(hi_u);
            const int n0 = tx * 8 + 2 * j;
            if (dlo >= 0.0f) {
                const float dx = px - s2x[n0], dy = py - s2y[n0];
                const float d = sqrtf(dx * dx + dy * dy);
                cnt++; dsum += d; dmin = fminf(dmin, d);
            }
            if (dhi >= 0.0f) {
                const float dx = px - s2x[n0 + 1], dy = py - s2y[n0 + 1];
                const float d = sqrtf(dx * dx + dy * dy);
                cnt++; dsum += d; dmin = fminf(dmin, d);
            }
        }
        // reduce across the 16 tx lanes (lane bits 0..3)
        #pragma unroll
        for (int off = 1; off < 16; off <<= 1) {
            cnt  += __shfl_xor_sync(0xffffffffu, cnt,  off);
            dsum += __shfl_xor_sync(0xffffffffu, dsum, off);
            dmin  = fminf(dmin, __shfl_xor_sync(0xffffffffu, dmin, off));
        }
        if (tx == 0) {
            const int idx = (o * NP + p) * NTILES + nt;
            g_cnt[idx]  = cnt;
            g_dsum[idx] = dsum;
            g_dmin[idx] = dmin;
        }
    }
}

// =================================================================
// Kernel 4: combine tile partials -> chamfer costs -> scalar loss.
// Partials were just written by the gemm => L2-resident. Vectorized
// int4/float4 reads (16 consecutive tile entries per cell).
// =================================================================
__global__ __launch_bounds__(512)
void final_kernel(float* __restrict__ out) {
    __shared__ float red[512];
    const int tid = threadIdx.x;

    float local = 0.0f;
    #pragma unroll
    for (int it = 0; it < (NOBJ * NP) / 512; it++) {
        const int cell = it * 512 + tid;
        const int idx0 = cell * NTILES;
        int   cnt  = 0;
        float dsum = 0.0f;
        float dmin = 3.402823466e38f;
        #pragma unroll
        for (int t = 0; t < NTILES; t += 4) {
            const int4   c4 = *(const int4*)  (g_cnt  + idx0 + t);
            const float4 s4 = *(const float4*)(g_dsum + idx0 + t);
            const float4 m4 = *(const float4*)(g_dmin + idx0 + t);
            cnt  += c4.x + c4.y + c4.z + c4.w;
            dsum += s4.x + s4.y + s4.z + s4.w;
            dmin  = fminf(dmin, fminf(fminf(m4.x, m4.y), fminf(m4.z, m4.w)));
        }
        if (cnt > 0)
            local += 0.5f * (dmin + dsum / (float)cnt) * g_m[cell >> 7];
    }
    red[tid] = local;
    __syncthreads();
    for (int s = 256; s > 0; s >>= 1) {
        if (tid < s) red[tid] += red[tid + s];
        __syncthreads();
    }
    if (tid == 0) out[0] = red[0] * (1.0f / (float)(NOBJ * NP));
}

// =================================================================
// kernel_launch: 5 launches, graph-capturable, no allocations.
// =================================================================
extern "C" void kernel_launch(void* const* d_in, const int* in_sizes, int n_in,
                              void* d_out, int out_size) {
    // Identify inputs by element count (robust to index assumptions):
    //   point_set_1: 16*128*2  = 4096   (first 4096-sized input)
    //   point_set_2: 16*2048*2 = 65536
    //   feats:       256*384*384 = 37748736
    //   key_points:  2048*2    = 4096   (second 4096-sized input)
    const float* ps1   = nullptr;
    const float* ps2   = nullptr;
    const float* feats = nullptr;
    const float* kp    = nullptr;
    for (int i = 0; i < n_in; i++) {
        if (in_sizes[i] == 37748736)      feats = (const float*)d_in[i];
        else if (in_sizes[i] == 65536)    ps2   = (const float*)d_in[i];
        else if (in_sizes[i] == 4096) {
            if (!ps1) ps1 = (const float*)d_in[i];
            else      kp  = (const float*)d_in[i];
        }
    }
    float* out = (float*)d_out;

    m_kernel<<<NOBJ, 256>>>(ps2);                                // off critical path
    transpose_kernel<<<dim3(HWd / 32, Cd / 32), dim3(8, 32)>>>(feats);
    sample_kernel<<<NPTS / 4, dim3(64, 4)>>>(kp, ps2);
    gemm_mask_kernel<<<dim3(NTILES, NOBJ), 256>>>(ps1, ps2);
    final_kernel<<<1, 512>>>(out);
}

// round 7
// speedup vs baseline: 1.1582x; 1.0422x over previous
#include <cuda_runtime.h>
#include <cstdint>

// ---------------- problem constants ----------------
#define Wd   384
#define Hd   384
#define Cd   256
#define HWd  (Wd * Hd)          // 147456
#define NOBJ 16
#define NP   128
#define NN   2048
#define NKP  2048               // N_OBJ * N_P key points
#define NPTS (NKP + NOBJ * NN)  // 34816 total sampled points
#define NTILES 16               // 2048 / 128 n-tiles per object

// ---------------- device scratch (static: no allocations allowed) ----------------
__device__ float g_imgT[(size_t)HWd * Cd];      // [s][c]  (151 MB, transposed image)
__device__ float g_F[(size_t)NPTS * Cd];        // [pt][c] sampled features (35.7 MB)
__device__ int   g_cnt [NOBJ * NP * NTILES];    // per (o,p,ntile) partials
__device__ float g_dsum[NOBJ * NP * NTILES];
__device__ float g_dmin[NOBJ * NP * NTILES];
__device__ float g_m[NOBJ];                     // per-object validity mask

// =================================================================
// Kernel 0: m[o] = (sum(point_set_2[o]) >= 0). 16 blocks, float4.
// =================================================================
__global__ __launch_bounds__(256)
void m_kernel(const float* __restrict__ ps2) {
    __shared__ float red[8];
    const int o   = blockIdx.x;
    const int tid = threadIdx.x;
    const float4* p = (const float4*)(ps2 + (size_t)o * (NN * 2));
    float s = 0.0f;
    #pragma unroll
    for (int i = 0; i < 16; i++) {          // 4096 float4 / 256 threads
        const float4 v = p[tid + i * 256];
        s += v.x + v.y + v.z + v.w;
    }
    #pragma unroll
    for (int off = 16; off; off >>= 1) s += __shfl_xor_sync(0xffffffffu, s, off);
    if ((tid & 31) == 0) red[tid >> 5] = s;
    __syncthreads();
    if (tid == 0) {
        float t = 0.0f;
        #pragma unroll
        for (int w = 0; w < 8; w++) t += red[w];
        g_m[o] = (t >= 0.0f) ? 1.0f : 0.0f;
    }
}

// =================================================================
// Kernel 1: transpose feats [C,H,W] -> g_imgT [H*W, C]
// =================================================================
__global__ void transpose_kernel(const float* __restrict__ in) {
    __shared__ float tile[32][33];
    const int bs = blockIdx.x * 32;     // s base (pixel index)
    const int bc = blockIdx.y * 32;     // c base
    const int tx = threadIdx.x;         // 0..7
    const int ty = threadIdx.y;         // 0..31

    const float4 v = *(const float4*)(in + (size_t)(bc + ty) * HWd + bs + tx * 4);
    tile[ty][tx * 4 + 0] = v.x;
    tile[ty][tx * 4 + 1] = v.y;
    tile[ty][tx * 4 + 2] = v.z;
    tile[ty][tx * 4 + 3] = v.w;
    __syncthreads();

    float4 w;
    w.x = tile[tx * 4 + 0][ty];
    w.y = tile[tx * 4 + 1][ty];
    w.z = tile[tx * 4 + 2][ty];
    w.w = tile[tx * 4 + 3][ty];
    *(float4*)(g_imgT + (size_t)(bs + ty) * Cd + bc + tx * 4) = w;
}

// =================================================================
// Kernel 2: bilinear grid-sample all 34816 points from g_imgT.
// =================================================================
__global__ void sample_kernel(const float* __restrict__ kp,
                              const float* __restrict__ ps2) {
    const int tx = threadIdx.x;                       // 0..63  channel quad
    const int pt = blockIdx.x * 4 + threadIdx.y;      // 0..34815

    const float* src = (pt < NKP) ? (kp + (size_t)pt * 2)
                                  : (ps2 + (size_t)(pt - NKP) * 2);
    const float px = src[0];
    const float py = src[1];

    const float gx = 2.0f * (px * (1.0f / 384.0f)) - 1.0f;
    const float gy = 2.0f * (py * (1.0f / 384.0f)) - 1.0f;
    const float x  = ((gx + 1.0f) * 384.0f - 1.0f) * 0.5f;
    const float y  = ((gy + 1.0f) * 384.0f - 1.0f) * 0.5f;

    const float x0f = floorf(x), y0f = floorf(y);
    const float wx1 = x - x0f,   wy1 = y - y0f;
    const float wx0 = 1.0f - wx1, wy0 = 1.0f - wy1;
    const int x0 = (int)x0f, y0 = (int)y0f;
    const int x1 = x0 + 1,   y1 = y0 + 1;

    const float vx0 = (x0 >= 0 && x0 < Wd) ? 1.0f : 0.0f;
    const float vx1 = (x1 >= 0 && x1 < Wd) ? 1.0f : 0.0f;
    const float vy0 = (y0 >= 0 && y0 < Hd) ? 1.0f : 0.0f;
    const float vy1 = (y1 >= 0 && y1 < Hd) ? 1.0f : 0.0f;

    const float w00 = wx0 * wy0 * vx0 * vy0;
    const float w10 = wx1 * wy0 * vx1 * vy0;
    const float w01 = wx0 * wy1 * vx0 * vy1;
    const float w11 = wx1 * wy1 * vx1 * vy1;

    const int xc0 = min(max(x0, 0), Wd - 1);
    const int xc1 = min(max(x1, 0), Wd - 1);
    const int yc0 = min(max(y0, 0), Hd - 1);
    const int yc1 = min(max(y1, 0), Hd - 1);

    const size_t coff = (size_t)tx * 4;
    const float4 t00 = *(const float4*)(g_imgT + ((size_t)(yc0 * Wd + xc0)) * Cd + coff);
    const float4 t10 = *(const float4*)(g_imgT + ((size_t)(yc0 * Wd + xc1)) * Cd + coff);
    const float4 t01 = *(const float4*)(g_imgT + ((size_t)(yc1 * Wd + xc0)) * Cd + coff);
    const float4 t11 = *(const float4*)(g_imgT + ((size_t)(yc1 * Wd + xc1)) * Cd + coff);

    float4 acc;
    acc.x = w00 * t00.x + w10 * t10.x + w01 * t01.x + w11 * t11.x;
    acc.y = w00 * t00.y + w10 * t10.y + w01 * t01.y + w11 * t11.y;
    acc.z = w00 * t00.z + w10 * t10.z + w01 * t01.z + w11 * t11.z;
    acc.w = w00 * t00.w + w10 * t10.w + w01 * t01.w + w11 * t11.w;

    *(float4*)(g_F + (size_t)pt * Cd + coff) = acc;
}

// =================================================================
// Kernel 3: fused GEMM(sign) + distance + masked reduction.
// DOUBLE-BUFFERED smem pipeline: gmem loads for tile t+1 are issued
// before computing tile t (full latency overlap), stores go to the
// alternate buffer, ONE __syncthreads per K-step (was two).
// __launch_bounds__(256,2) pins regs<=128 -> 2 CTAs/SM, whole grid
// resident in one wave.
// =================================================================
#define FMA2(d, a, b) \
    asm("fma.rn.f32x2 %0, %1, %2, %3;" : "=l"(d) : "l"(a), "l"(b), "l"(d))

__global__ __launch_bounds__(256, 2)
void gemm_mask_kernel(const float* __restrict__ ps1,
                      const float* __restrict__ ps2) {
    __shared__ unsigned long long As2[2][8][130]; // A duplicated into f32x2 pairs
    __shared__ float Bs[2][8][132];
    __shared__ float s1x[128], s1y[128], s2x[128], s2y[128];

    const int o  = blockIdx.y;
    const int nt = blockIdx.x;
    const int tid = threadIdx.x;
    const int tx = tid & 15;        // n micro-tile
    const int ty = tid >> 4;        // p micro-tile

    const float* A = g_F + (size_t)(o * 128) * Cd;                       // f1 rows
    const float* B = g_F + (size_t)(NKP + o * NN + nt * 128) * Cd;       // f2 rows

    if (tid < 128) {
        const size_t i1 = ((size_t)o * NP + tid) * 2;
        s1x[tid] = ps1[i1];
        s1y[tid] = ps1[i1 + 1];
        const size_t i2 = ((size_t)o * NN + nt * 128 + tid) * 2;
        s2x[tid] = ps2[i2];
        s2y[tid] = ps2[i2 + 1];
    }

    unsigned long long acc[8][4];
    #pragma unroll
    for (int i = 0; i < 8; i++)
        #pragma unroll
        for (int j = 0; j < 4; j++) acc[i][j] = 0ull;

    const int lrow = tid >> 1;            // 0..127
    const int lk   = (tid & 1) * 4;       // 0 or 4
    const float* Ap = A + (size_t)lrow * Cd + lk;
    const float* Bp = B + (size_t)lrow * Cd + lk;

    // ---- prologue: stage tile 0 into buffer 0 ----
    {
        const float4 av = *(const float4*)(Ap);
        const float4 bv = *(const float4*)(Bp);
        unsigned long long d0, d1, d2, d3;
        asm("mov.b64 %0, {%1, %1};" : "=l"(d0) : "r"(__float_as_uint(av.x)));
        asm("mov.b64 %0, {%1, %1};" : "=l"(d1) : "r"(__float_as_uint(av.y)));
        asm("mov.b64 %0, {%1, %1};" : "=l"(d2) : "r"(__float_as_uint(av.z)));
        asm("mov.b64 %0, {%1, %1};" : "=l"(d3) : "r"(__float_as_uint(av.w)));
        As2[0][lk + 0][lrow] = d0;
        As2[0][lk + 1][lrow] = d1;
        As2[0][lk + 2][lrow] = d2;
        As2[0][lk + 3][lrow] = d3;
        Bs[0][lk + 0][lrow] = bv.x;
        Bs[0][lk + 1][lrow] = bv.y;
        Bs[0][lk + 2][lrow] = bv.z;
        Bs[0][lk + 3][lrow] = bv.w;
    }
    __syncthreads();

    #pragma unroll 2
    for (int k0 = 0; k0 < Cd; k0 += 8) {
        const int buf = (k0 >> 3) & 1;
        const bool more = (k0 + 8 < Cd);

        // issue next tile's global loads FIRST (latency hidden by compute)
        float4 av_n, bv_n;
        if (more) {
            av_n = *(const float4*)(Ap + k0 + 8);
            bv_n = *(const float4*)(Bp + k0 + 8);
        }

        // compute current tile
        #pragma unroll
        for (int kk = 0; kk < 8; kk++) {
            const ulonglong2* ap = (const ulonglong2*)&As2[buf][kk][ty * 8];
            const ulonglong2 a01 = ap[0], a23 = ap[1], a45 = ap[2], a67 = ap[3];
            const ulonglong2* bp = (const ulonglong2*)&Bs[buf][kk][tx * 8];
            const ulonglong2 b01 = bp[0], b23 = bp[1];
            const unsigned long long a[8] = {a01.x, a01.y, a23.x, a23.y,
                                             a45.x, a45.y, a67.x, a67.y};
            const unsigned long long b[4] = {b01.x, b01.y, b23.x, b23.y};
            #pragma unroll
            for (int i = 0; i < 8; i++)
                #pragma unroll
                for (int j = 0; j < 4; j++)
                    FMA2(acc[i][j], a[i], b[j]);
        }

        // stage next tile into the other buffer
        if (more) {
            const int nb = buf ^ 1;
            unsigned long long d0, d1, d2, d3;
            asm("mov.b64 %0, {%1, %1};" : "=l"(d0) : "r"(__float_as_uint(av_n.x)));
            asm("mov.b64 %0, {%1, %1};" : "=l"(d1) : "r"(__float_as_uint(av_n.y)));
            asm("mov.b64 %0, {%1, %1};" : "=l"(d2) : "r"(__float_as_uint(av_n.z)));
            asm("mov.b64 %0, {%1, %1};" : "=l"(d3) : "r"(__float_as_uint(av_n.w)));
            As2[nb][lk + 0][lrow] = d0;
            As2[nb][lk + 1][lrow] = d1;
            As2[nb][lk + 2][lrow] = d2;
            As2[nb][lk + 3][lrow] = d3;
            Bs[nb][lk + 0][lrow] = bv_n.x;
            Bs[nb][lk + 1][lrow] = bv_n.y;
            Bs[nb][lk + 2][lrow] = bv_n.z;
            Bs[nb][lk + 3][lrow] = bv_n.w;
        }
        __syncthreads();
    }

    // ---- epilogue: mask, distances, per-p reduction ----
    #pragma unroll
    for (int i = 0; i < 8; i++) {
        const int p = ty * 8 + i;
        const float px = s1x[p], py = s1y[p];
        int   cnt  = 0;
        float dsum = 0.0f;
        float dmin = 3.402823466e38f;
        #pragma unroll
        for (int j = 0; j < 4; j++) {
            unsigned lo_u, hi_u;
            asm("mov.b64 {%0, %1}, %2;" : "=r"(lo_u), "=r"(hi_u) : "l"(acc[i][j]));
            const float dlo = __uint_as_float(lo_u);
            const float dhi = __uint_as_float(hi_u);
            const int n0 = tx * 8 + 2 * j;
            if (dlo >= 0.0f) {
                const float dx = px - s2x[n0], dy = py - s2y[n0];
                const float d = sqrtf(dx * dx + dy * dy);
                cnt++; dsum += d; dmin = fminf(dmin, d);
            }
            if (dhi >= 0.0f) {
                const float dx = px - s2x[n0 + 1], dy = py - s2y[n0 + 1];
                const float d = sqrtf(dx * dx + dy * dy);
                cnt++; dsum += d; dmin = fminf(dmin, d);
            }
        }
        #pragma unroll
        for (int off = 1; off < 16; off <<= 1) {
            cnt  += __shfl_xor_sync(0xffffffffu, cnt,  off);
            dsum += __shfl_xor_sync(0xffffffffu, dsum, off);
            dmin  = fminf(dmin, __shfl_xor_sync(0xffffffffu, dmin, off));
        }
        if (tx == 0) {
            const int idx = (o * NP + p) * NTILES + nt;
            g_cnt[idx]  = cnt;
            g_dsum[idx] = dsum;
            g_dmin[idx] = dmin;
        }
    }
}

// =================================================================
// Kernel 4: combine tile partials -> chamfer costs -> scalar loss.
// =================================================================
__global__ __launch_bounds__(512)
void final_kernel(float* __restrict__ out) {
    __shared__ float red[512];
    const int tid = threadIdx.x;

    float local = 0.0f;
    #pragma unroll
    for (int it = 0; it < (NOBJ * NP) / 512; it++) {
        const int cell = it * 512 + tid;
        const int idx0 = cell * NTILES;
        int   cnt  = 0;
        float dsum = 0.0f;
        float dmin = 3.402823466e38f;
        #pragma unroll
        for (int t = 0; t < NTILES; t += 4) {
            const int4   c4 = *(const int4*)  (g_cnt  + idx0 + t);
            const float4 s4 = *(const float4*)(g_dsum + idx0 + t);
            const float4 m4 = *(const float4*)(g_dmin + idx0 + t);
            cnt  += c4.x + c4.y + c4.z + c4.w;
            dsum += s4.x + s4.y + s4.z + s4.w;
            dmin  = fminf(dmin, fminf(fminf(m4.x, m4.y), fminf(m4.z, m4.w)));
        }
        if (cnt > 0)
            local += 0.5f * (dmin + dsum / (float)cnt) * g_m[cell >> 7];
    }
    red[tid] = local;
    __syncthreads();
    for (int s = 256; s > 0; s >>= 1) {
        if (tid < s) red[tid] += red[tid + s];
        __syncthreads();
    }
    if (tid == 0) out[0] = red[0] * (1.0f / (float)(NOBJ * NP));
}

// =================================================================
// kernel_launch: 5 launches, graph-capturable, no allocations.
// =================================================================
extern "C" void kernel_launch(void* const* d_in, const int* in_sizes, int n_in,
                              void* d_out, int out_size) {
    const float* ps1   = nullptr;
    const float* ps2   = nullptr;
    const float* feats = nullptr;
    const float* kp    = nullptr;
    for (int i = 0; i < n_in; i++) {
        if (in_sizes[i] == 37748736)      feats = (const float*)d_in[i];
        else if (in_sizes[i] == 65536)    ps2   = (const float*)d_in[i];
        else if (in_sizes[i] == 4096) {
            if (!ps1) ps1 = (const float*)d_in[i];
            else      kp  = (const float*)d_in[i];
        }
    }
    float* out = (float*)d_out;

    m_kernel<<<NOBJ, 256>>>(ps2);                                // off critical path
    transpose_kernel<<<dim3(HWd / 32, Cd / 32), dim3(8, 32)>>>(feats);
    sample_kernel<<<NPTS / 4, dim3(64, 4)>>>(kp, ps2);
    gemm_mask_kernel<<<dim3(NTILES, NOBJ), 256>>>(ps1, ps2);
    final_kernel<<<1, 512>>>(out);
}

// round 8
// speedup vs baseline: 1.3213x; 1.1408x over previous
#include <cuda_runtime.h>
#include <cstdint>

// ---------------- problem constants ----------------
#define Wd   384
#define Hd   384
#define Cd   256
#define HWd  (Wd * Hd)          // 147456
#define NOBJ 16
#define NP   128
#define NN   2048
#define NKP  2048               // N_OBJ * N_P key points
#define NPTS (NKP + NOBJ * NN)  // 34816 total sampled points
#define NTILES 16               // 2048 / 128 n-tiles per object

// ---------------- device scratch (static: no allocations allowed) ----------------
__device__ float g_imgT[(size_t)HWd * Cd];      // [s][c]  (151 MB, transposed image)
__device__ float g_F[(size_t)NPTS * Cd];        // [pt][c] sampled features (35.7 MB)
__device__ int   g_cnt [NOBJ * NP * NTILES];    // per (o,p,ntile) partials
__device__ float g_dsum[NOBJ * NP * NTILES];
__device__ float g_dmin[NOBJ * NP * NTILES];
__device__ float g_m[NOBJ];                     // per-object validity mask

// =================================================================
// Kernel 0: m[o] = (sum(point_set_2[o]) >= 0). 16 blocks, float4.
// =================================================================
__global__ __launch_bounds__(256)
void m_kernel(const float* __restrict__ ps2) {
    __shared__ float red[8];
    const int o   = blockIdx.x;
    const int tid = threadIdx.x;
    const float4* p = (const float4*)(ps2 + (size_t)o * (NN * 2));
    float s = 0.0f;
    #pragma unroll
    for (int i = 0; i < 16; i++) {
        const float4 v = p[tid + i * 256];
        s += v.x + v.y + v.z + v.w;
    }
    #pragma unroll
    for (int off = 16; off; off >>= 1) s += __shfl_xor_sync(0xffffffffu, s, off);
    if ((tid & 31) == 0) red[tid >> 5] = s;
    __syncthreads();
    if (tid == 0) {
        float t = 0.0f;
        #pragma unroll
        for (int w = 0; w < 8; w++) t += red[w];
        g_m[o] = (t >= 0.0f) ? 1.0f : 0.0f;
    }
}

// =================================================================
// Kernel 1: transpose feats [C,H,W] -> g_imgT [H*W, C]
// =================================================================
__global__ void transpose_kernel(const float* __restrict__ in) {
    __shared__ float tile[32][33];
    const int bs = blockIdx.x * 32;
    const int bc = blockIdx.y * 32;
    const int tx = threadIdx.x;         // 0..7
    const int ty = threadIdx.y;         // 0..31

    const float4 v = *(const float4*)(in + (size_t)(bc + ty) * HWd + bs + tx * 4);
    tile[ty][tx * 4 + 0] = v.x;
    tile[ty][tx * 4 + 1] = v.y;
    tile[ty][tx * 4 + 2] = v.z;
    tile[ty][tx * 4 + 3] = v.w;
    __syncthreads();

    float4 w;
    w.x = tile[tx * 4 + 0][ty];
    w.y = tile[tx * 4 + 1][ty];
    w.z = tile[tx * 4 + 2][ty];
    w.w = tile[tx * 4 + 3][ty];
    *(float4*)(g_imgT + (size_t)(bs + ty) * Cd + bc + tx * 4) = w;
}

// =================================================================
// Kernel 2: bilinear grid-sample all 34816 points from g_imgT.
// =================================================================
__global__ void sample_kernel(const float* __restrict__ kp,
                              const float* __restrict__ ps2) {
    const int tx = threadIdx.x;                       // 0..63  channel quad
    const int pt = blockIdx.x * 4 + threadIdx.y;      // 0..34815

    const float* src = (pt < NKP) ? (kp + (size_t)pt * 2)
                                  : (ps2 + (size_t)(pt - NKP) * 2);
    const float px = src[0];
    const float py = src[1];

    const float gx = 2.0f * (px * (1.0f / 384.0f)) - 1.0f;
    const float gy = 2.0f * (py * (1.0f / 384.0f)) - 1.0f;
    const float x  = ((gx + 1.0f) * 384.0f - 1.0f) * 0.5f;
    const float y  = ((gy + 1.0f) * 384.0f - 1.0f) * 0.5f;

    const float x0f = floorf(x), y0f = floorf(y);
    const float wx1 = x - x0f,   wy1 = y - y0f;
    const float wx0 = 1.0f - wx1, wy0 = 1.0f - wy1;
    const int x0 = (int)x0f, y0 = (int)y0f;
    const int x1 = x0 + 1,   y1 = y0 + 1;

    const float vx0 = (x0 >= 0 && x0 < Wd) ? 1.0f : 0.0f;
    const float vx1 = (x1 >= 0 && x1 < Wd) ? 1.0f : 0.0f;
    const float vy0 = (y0 >= 0 && y0 < Hd) ? 1.0f : 0.0f;
    const float vy1 = (y1 >= 0 && y1 < Hd) ? 1.0f : 0.0f;

    const float w00 = wx0 * wy0 * vx0 * vy0;
    const float w10 = wx1 * wy0 * vx1 * vy0;
    const float w01 = wx0 * wy1 * vx0 * vy1;
    const float w11 = wx1 * wy1 * vx1 * vy1;

    const int xc0 = min(max(x0, 0), Wd - 1);
    const int xc1 = min(max(x1, 0), Wd - 1);
    const int yc0 = min(max(y0, 0), Hd - 1);
    const int yc1 = min(max(y1, 0), Hd - 1);

    const size_t coff = (size_t)tx * 4;
    const float4 t00 = *(const float4*)(g_imgT + ((size_t)(yc0 * Wd + xc0)) * Cd + coff);
    const float4 t10 = *(const float4*)(g_imgT + ((size_t)(yc0 * Wd + xc1)) * Cd + coff);
    const float4 t01 = *(const float4*)(g_imgT + ((size_t)(yc1 * Wd + xc0)) * Cd + coff);
    const float4 t11 = *(const float4*)(g_imgT + ((size_t)(yc1 * Wd + xc1)) * Cd + coff);

    float4 acc;
    acc.x = w00 * t00.x + w10 * t10.x + w01 * t01.x + w11 * t11.x;
    acc.y = w00 * t00.y + w10 * t10.y + w01 * t01.y + w11 * t11.y;
    acc.z = w00 * t00.z + w10 * t10.z + w01 * t01.z + w11 * t11.z;
    acc.w = w00 * t00.w + w10 * t10.w + w01 * t01.w + w11 * t11.w;

    *(float4*)(g_F + (size_t)pt * Cd + coff) = acc;
}

// =================================================================
// Kernel 3: fused GEMM(sign) + distance + masked reduction.
// LSU-optimized: A stored as plain fp32 in smem (dup to f32x2 in
// registers, ALU pipe), B ownership re-mapped so each thread's two
// LDS.128 hit 16 contiguous granules (conflict-free). 4 LDS.128 /
// kk / thread (was 6, with 4-way conflicts). Double-buffered, one
// barrier per K-step.
// Thread (tx,ty) owns p = ty*8..ty*8+7, n = {tx*4..+3, 64+tx*4..+3}.
// =================================================================
#define FMA2(d, a, b) \
    asm("fma.rn.f32x2 %0, %1, %2, %3;" : "=l"(d) : "l"(a), "l"(b), "l"(d))
#define DUP2(d, s) \
    asm("mov.b64 %0, {%1, %1};" : "=l"(d) : "r"(__float_as_uint(s)))

__global__ __launch_bounds__(256, 2)
void gemm_mask_kernel(const float* __restrict__ ps1,
                      const float* __restrict__ ps2) {
    __shared__ float As[2][8][132];
    __shared__ float Bs[2][8][132];
    __shared__ float s1x[128], s1y[128], s2x[128], s2y[128];

    const int o  = blockIdx.y;
    const int nt = blockIdx.x;
    const int tid = threadIdx.x;
    const int tx = tid & 15;        // n micro-tile
    const int ty = tid >> 4;        // p micro-tile

    const float* A = g_F + (size_t)(o * 128) * Cd;                       // f1 rows
    const float* B = g_F + (size_t)(NKP + o * NN + nt * 128) * Cd;       // f2 rows

    if (tid < 128) {
        const size_t i1 = ((size_t)o * NP + tid) * 2;
        s1x[tid] = ps1[i1];
        s1y[tid] = ps1[i1 + 1];
        const size_t i2 = ((size_t)o * NN + nt * 128 + tid) * 2;
        s2x[tid] = ps2[i2];
        s2y[tid] = ps2[i2 + 1];
    }

    unsigned long long acc[8][4];
    #pragma unroll
    for (int i = 0; i < 8; i++)
        #pragma unroll
        for (int j = 0; j < 4; j++) acc[i][j] = 0ull;

    const int lrow = tid >> 1;            // 0..127
    const int lk   = (tid & 1) * 4;       // 0 or 4
    const float* Ap = A + (size_t)lrow * Cd + lk;
    const float* Bp = B + (size_t)lrow * Cd + lk;

    // ---- prologue: stage tile 0 into buffer 0 ----
    {
        const float4 av = *(const float4*)(Ap);
        const float4 bv = *(const float4*)(Bp);
        As[0][lk + 0][lrow] = av.x;
        As[0][lk + 1][lrow] = av.y;
        As[0][lk + 2][lrow] = av.z;
        As[0][lk + 3][lrow] = av.w;
        Bs[0][lk + 0][lrow] = bv.x;
        Bs[0][lk + 1][lrow] = bv.y;
        Bs[0][lk + 2][lrow] = bv.z;
        Bs[0][lk + 3][lrow] = bv.w;
    }
    __syncthreads();

    #pragma unroll 2
    for (int k0 = 0; k0 < Cd; k0 += 8) {
        const int buf = (k0 >> 3) & 1;
        const bool more = (k0 + 8 < Cd);

        // issue next tile's global loads FIRST (latency hidden by compute)
        float4 av_n, bv_n;
        if (more) {
            av_n = *(const float4*)(Ap + k0 + 8);
            bv_n = *(const float4*)(Bp + k0 + 8);
        }

        // compute current tile
        #pragma unroll
        for (int kk = 0; kk < 8; kk++) {
            // A: 2x LDS.128, 2 distinct addrs per warp (broadcast)
            const float4 alo = *(const float4*)&As[buf][kk][ty * 8];
            const float4 ahi = *(const float4*)&As[buf][kk][ty * 8 + 4];
            // B: 2x LDS.128, 16 contiguous granules per warp (conflict-free)
            const ulonglong2 bL = *(const ulonglong2*)&Bs[buf][kk][tx * 4];
            const ulonglong2 bH = *(const ulonglong2*)&Bs[buf][kk][64 + tx * 4];

            unsigned long long a2[8];
            DUP2(a2[0], alo.x); DUP2(a2[1], alo.y);
            DUP2(a2[2], alo.z); DUP2(a2[3], alo.w);
            DUP2(a2[4], ahi.x); DUP2(a2[5], ahi.y);
            DUP2(a2[6], ahi.z); DUP2(a2[7], ahi.w);

            #pragma unroll
            for (int i = 0; i < 8; i++) {
                FMA2(acc[i][0], a2[i], bL.x);
                FMA2(acc[i][1], a2[i], bL.y);
                FMA2(acc[i][2], a2[i], bH.x);
                FMA2(acc[i][3], a2[i], bH.y);
            }
        }

        // stage next tile into the other buffer
        if (more) {
            const int nb = buf ^ 1;
            As[nb][lk + 0][lrow] = av_n.x;
            As[nb][lk + 1][lrow] = av_n.y;
            As[nb][lk + 2][lrow] = av_n.z;
            As[nb][lk + 3][lrow] = av_n.w;
            Bs[nb][lk + 0][lrow] = bv_n.x;
            Bs[nb][lk + 1][lrow] = bv_n.y;
            Bs[nb][lk + 2][lrow] = bv_n.z;
            Bs[nb][lk + 3][lrow] = bv_n.w;
        }
        __syncthreads();
    }

    // ---- epilogue: mask, distances, per-p reduction ----
    // acc[i][j] pair lanes map to n:
    //   j=0: tx*4+0, tx*4+1   j=1: tx*4+2, tx*4+3
    //   j=2: 64+tx*4+0, +1    j=3: 64+tx*4+2, +3
    #pragma unroll
    for (int i = 0; i < 8; i++) {
        const int p = ty * 8 + i;
        const float px = s1x[p], py = s1y[p];
        int   cnt  = 0;
        float dsum = 0.0f;
        float dmin = 3.402823466e38f;
        #pragma unroll
        for (int j = 0; j < 4; j++) {
            unsigned lo_u, hi_u;
            asm("mov.b64 {%0, %1}, %2;" : "=r"(lo_u), "=r"(hi_u) : "l"(acc[i][j]));
            const float dlo = __uint_as_float(lo_u);
            const float dhi = __uint_as_float(hi_u);
            const int n0 = (j < 2) ? (tx * 4 + 2 * j) : (64 + tx * 4 + 2 * (j - 2));
            if (dlo >= 0.0f) {
                const float dx = px - s2x[n0], dy = py - s2y[n0];
                const float d = sqrtf(dx * dx + dy * dy);
                cnt++; dsum += d; dmin = fminf(dmin, d);
            }
            if (dhi >= 0.0f) {
                const float dx = px - s2x[n0 + 1], dy = py - s2y[n0 + 1];
                const float d = sqrtf(dx * dx + dy * dy);
                cnt++; dsum += d; dmin = fminf(dmin, d);
            }
        }
        #pragma unroll
        for (int off = 1; off < 16; off <<= 1) {
            cnt  += __shfl_xor_sync(0xffffffffu, cnt,  off);
            dsum += __shfl_xor_sync(0xffffffffu, dsum, off);
            dmin  = fminf(dmin, __shfl_xor_sync(0xffffffffu, dmin, off));
        }
        if (tx == 0) {
            const int idx = (o * NP + p) * NTILES + nt;
            g_cnt[idx]  = cnt;
            g_dsum[idx] = dsum;
            g_dmin[idx] = dmin;
        }
    }
}

// =================================================================
// Kernel 4: combine tile partials -> chamfer costs -> scalar loss.
// =================================================================
__global__ __launch_bounds__(512)
void final_kernel(float* __restrict__ out) {
    __shared__ float red[512];
    const int tid = threadIdx.x;

    float local = 0.0f;
    #pragma unroll
    for (int it = 0; it < (NOBJ * NP) / 512; it++) {
        const int cell = it * 512 + tid;
        const int idx0 = cell * NTILES;
        int   cnt  = 0;
        float dsum = 0.0f;
        float dmin = 3.402823466e38f;
        #pragma unroll
        for (int t = 0; t < NTILES; t += 4) {
            const int4   c4 = *(const int4*)  (g_cnt  + idx0 + t);
            const float4 s4 = *(const float4*)(g_dsum + idx0 + t);
            const float4 m4 = *(const float4*)(g_dmin + idx0 + t);
            cnt  += c4.x + c4.y + c4.z + c4.w;
            dsum += s4.x + s4.y + s4.z + s4.w;
            dmin  = fminf(dmin, fminf(fminf(m4.x, m4.y), fminf(m4.z, m4.w)));
        }
        if (cnt > 0)
            local += 0.5f * (dmin + dsum / (float)cnt) * g_m[cell >> 7];
    }
    red[tid] = local;
    __syncthreads();
    for (int s = 256; s > 0; s >>= 1) {
        if (tid < s) red[tid] += red[tid + s];
        __syncthreads();
    }
    if (tid == 0) out[0] = red[0] * (1.0f / (float)(NOBJ * NP));
}

// =================================================================
// kernel_launch: 5 launches, graph-capturable, no allocations.
// =================================================================
extern "C" void kernel_launch(void* const* d_in, const int* in_sizes, int n_in,
                              void* d_out, int out_size) {
    const float* ps1   = nullptr;
    const float* ps2   = nullptr;
    const float* feats = nullptr;
    const float* kp    = nullptr;
    for (int i = 0; i < n_in; i++) {
        if (in_sizes[i] == 37748736)      feats = (const float*)d_in[i];
        else if (in_sizes[i] == 65536)    ps2   = (const float*)d_in[i];
        else if (in_sizes[i] == 4096) {
            if (!ps1) ps1 = (const float*)d_in[i];
            else      kp  = (const float*)d_in[i];
        }
    }
    float* out = (float*)d_out;

    m_kernel<<<NOBJ, 256>>>(ps2);
    transpose_kernel<<<dim3(HWd / 32, Cd / 32), dim3(8, 32)>>>(feats);
    sample_kernel<<<NPTS / 4, dim3(64, 4)>>>(kp, ps2);
    gemm_mask_kernel<<<dim3(NTILES, NOBJ), 256>>>(ps1, ps2);
    final_kernel<<<1, 512>>>(out);
}

// round 9
// speedup vs baseline: 1.5138x; 1.1457x over previous
#include <cuda_runtime.h>
#include <cuda_bf16.h>
#include <cstdint>

// ---------------- problem constants ----------------
#define Wd   384
#define Hd   384
#define Cd   256
#define HWd  (Wd * Hd)          // 147456
#define NOBJ 16
#define NP   128
#define NN   2048
#define NKP  2048               // N_OBJ * N_P key points
#define NPTS (NKP + NOBJ * NN)  // 34816 total sampled points
#define NTILES 16               // 2048 / 128 n-tiles per object

// ---------------- device scratch (static: no allocations allowed) ----------------
__device__ __nv_bfloat16 g_imgTh[(size_t)HWd * Cd]; // [s][c] transposed image, bf16 (75 MB)
__device__ float g_F[(size_t)NPTS * Cd];            // [pt][c] sampled features fp32 (35.7 MB)
__device__ int   g_cnt [NOBJ * NP * NTILES];
__device__ float g_dsum[NOBJ * NP * NTILES];
__device__ float g_dmin[NOBJ * NP * NTILES];
__device__ float g_m[NOBJ];

// =================================================================
// Kernel 0: m[o] = (sum(point_set_2[o]) >= 0). 16 blocks, float4.
// =================================================================
__global__ __launch_bounds__(256)
void m_kernel(const float* __restrict__ ps2) {
    __shared__ float red[8];
    const int o   = blockIdx.x;
    const int tid = threadIdx.x;
    const float4* p = (const float4*)(ps2 + (size_t)o * (NN * 2));
    float s = 0.0f;
    #pragma unroll
    for (int i = 0; i < 16; i++) {
        const float4 v = p[tid + i * 256];
        s += v.x + v.y + v.z + v.w;
    }
    #pragma unroll
    for (int off = 16; off; off >>= 1) s += __shfl_xor_sync(0xffffffffu, s, off);
    if ((tid & 31) == 0) red[tid >> 5] = s;
    __syncthreads();
    if (tid == 0) {
        float t = 0.0f;
        #pragma unroll
        for (int w = 0; w < 8; w++) t += red[w];
        g_m[o] = (t >= 0.0f) ? 1.0f : 0.0f;
    }
}

// =================================================================
// Kernel 1: transpose feats [C,H,W] -> g_imgTh [H*W, C] in bf16.
// 32x32 tile; float4 global loads, 8B bf16x4 stores.
// =================================================================
__global__ void transpose_kernel(const float* __restrict__ in) {
    __shared__ float tile[32][33];
    const int bs = blockIdx.x * 32;     // s base (pixel index)
    const int bc = blockIdx.y * 32;     // c base
    const int tx = threadIdx.x;         // 0..7
    const int ty = threadIdx.y;         // 0..31

    const float4 v = *(const float4*)(in + (size_t)(bc + ty) * HWd + bs + tx * 4);
    tile[ty][tx * 4 + 0] = v.x;
    tile[ty][tx * 4 + 1] = v.y;
    tile[ty][tx * 4 + 2] = v.z;
    tile[ty][tx * 4 + 3] = v.w;
    __syncthreads();

    const float w0 = tile[tx * 4 + 0][ty];
    const float w1 = tile[tx * 4 + 1][ty];
    const float w2 = tile[tx * 4 + 2][ty];
    const float w3 = tile[tx * 4 + 3][ty];
    uint2 o;
    {
        const __nv_bfloat162 lo = __floats2bfloat162_rn(w0, w1);
        const __nv_bfloat162 hi = __floats2bfloat162_rn(w2, w3);
        o.x = *(const unsigned*)&lo;
        o.y = *(const unsigned*)&hi;
    }
    *(uint2*)(g_imgTh + (size_t)(bs + ty) * Cd + bc + tx * 4) = o;
}

// =================================================================
// Kernel 2: bilinear grid-sample all 34816 points from bf16 g_imgTh.
// Block = 8 points x 32 lanes (8 channels each). Taps are 512 B
// contiguous per warp (uint4 per lane); blend in fp32; g_F fp32.
// =================================================================
__global__ __launch_bounds__(256)
void sample_kernel(const float* __restrict__ kp,
                   const float* __restrict__ ps2) {
    const int lane = threadIdx.x;                     // 0..31, 8 channels each
    const int pt   = blockIdx.x * 8 + threadIdx.y;    // 0..34815

    const float* src = (pt < NKP) ? (kp + (size_t)pt * 2)
                                  : (ps2 + (size_t)(pt - NKP) * 2);
    const float px = src[0];
    const float py = src[1];

    // exact reference math (grid_sample, align_corners=False)
    const float gx = 2.0f * (px * (1.0f / 384.0f)) - 1.0f;
    const float gy = 2.0f * (py * (1.0f / 384.0f)) - 1.0f;
    const float x  = ((gx + 1.0f) * 384.0f - 1.0f) * 0.5f;
    const float y  = ((gy + 1.0f) * 384.0f - 1.0f) * 0.5f;

    const float x0f = floorf(x), y0f = floorf(y);
    const float wx1 = x - x0f,   wy1 = y - y0f;
    const float wx0 = 1.0f - wx1, wy0 = 1.0f - wy1;
    const int x0 = (int)x0f, y0 = (int)y0f;
    const int x1 = x0 + 1,   y1 = y0 + 1;

    const float vx0 = (x0 >= 0 && x0 < Wd) ? 1.0f : 0.0f;
    const float vx1 = (x1 >= 0 && x1 < Wd) ? 1.0f : 0.0f;
    const float vy0 = (y0 >= 0 && y0 < Hd) ? 1.0f : 0.0f;
    const float vy1 = (y1 >= 0 && y1 < Hd) ? 1.0f : 0.0f;

    const float w00 = wx0 * wy0 * vx0 * vy0;
    const float w10 = wx1 * wy0 * vx1 * vy0;
    const float w01 = wx0 * wy1 * vx0 * vy1;
    const float w11 = wx1 * wy1 * vx1 * vy1;

    const int xc0 = min(max(x0, 0), Wd - 1);
    const int xc1 = min(max(x1, 0), Wd - 1);
    const int yc0 = min(max(y0, 0), Hd - 1);
    const int yc1 = min(max(y1, 0), Hd - 1);

    const size_t coff = (size_t)lane * 8;
    const uint4 r00 = *(const uint4*)(g_imgTh + ((size_t)(yc0 * Wd + xc0)) * Cd + coff);
    const uint4 r10 = *(const uint4*)(g_imgTh + ((size_t)(yc0 * Wd + xc1)) * Cd + coff);
    const uint4 r01 = *(const uint4*)(g_imgTh + ((size_t)(yc1 * Wd + xc0)) * Cd + coff);
    const uint4 r11 = *(const uint4*)(g_imgTh + ((size_t)(yc1 * Wd + xc1)) * Cd + coff);

    float out[8];
    #pragma unroll
    for (int q = 0; q < 4; q++) {
        const unsigned u00 = (&r00.x)[q];
        const unsigned u10 = (&r10.x)[q];
        const unsigned u01 = (&r01.x)[q];
        const unsigned u11 = (&r11.x)[q];
        const float2 f00 = __bfloat1622float2(*(const __nv_bfloat162*)&u00);
        const float2 f10 = __bfloat1622float2(*(const __nv_bfloat162*)&u10);
        const float2 f01 = __bfloat1622float2(*(const __nv_bfloat162*)&u01);
        const float2 f11 = __bfloat1622float2(*(const __nv_bfloat162*)&u11);
        out[q * 2 + 0] = w00 * f00.x + w10 * f10.x + w01 * f01.x + w11 * f11.x;
        out[q * 2 + 1] = w00 * f00.y + w10 * f10.y + w01 * f01.y + w11 * f11.y;
    }

    float* dst = g_F + (size_t)pt * Cd + coff;
    *(float4*)(dst)     = make_float4(out[0], out[1], out[2], out[3]);
    *(float4*)(dst + 4) = make_float4(out[4], out[5], out[6], out[7]);
}

// =================================================================
// Kernel 3: fused GEMM(sign) + distance + masked reduction.
// (unchanged from R8 — 54.7us, fma 51%)
// =================================================================
#define FMA2(d, a, b) \
    asm("fma.rn.f32x2 %0, %1, %2, %3;" : "=l"(d) : "l"(a), "l"(b), "l"(d))
#define DUP2(d, s) \
    asm("mov.b64 %0, {%1, %1};" : "=l"(d) : "r"(__float_as_uint(s)))

__global__ __launch_bounds__(256, 2)
void gemm_mask_kernel(const float* __restrict__ ps1,
                      const float* __restrict__ ps2) {
    __shared__ float As[2][8][132];
    __shared__ float Bs[2][8][132];
    __shared__ float s1x[128], s1y[128], s2x[128], s2y[128];

    const int o  = blockIdx.y;
    const int nt = blockIdx.x;
    const int tid = threadIdx.x;
    const int tx = tid & 15;        // n micro-tile
    const int ty = tid >> 4;        // p micro-tile

    const float* A = g_F + (size_t)(o * 128) * Cd;                       // f1 rows
    const float* B = g_F + (size_t)(NKP + o * NN + nt * 128) * Cd;       // f2 rows

    if (tid < 128) {
        const size_t i1 = ((size_t)o * NP + tid) * 2;
        s1x[tid] = ps1[i1];
        s1y[tid] = ps1[i1 + 1];
        const size_t i2 = ((size_t)o * NN + nt * 128 + tid) * 2;
        s2x[tid] = ps2[i2];
        s2y[tid] = ps2[i2 + 1];
    }

    unsigned long long acc[8][4];
    #pragma unroll
    for (int i = 0; i < 8; i++)
        #pragma unroll
        for (int j = 0; j < 4; j++) acc[i][j] = 0ull;

    const int lrow = tid >> 1;            // 0..127
    const int lk   = (tid & 1) * 4;       // 0 or 4
    const float* Ap = A + (size_t)lrow * Cd + lk;
    const float* Bp = B + (size_t)lrow * Cd + lk;

    // ---- prologue: stage tile 0 into buffer 0 ----
    {
        const float4 av = *(const float4*)(Ap);
        const float4 bv = *(const float4*)(Bp);
        As[0][lk + 0][lrow] = av.x;
        As[0][lk + 1][lrow] = av.y;
        As[0][lk + 2][lrow] = av.z;
        As[0][lk + 3][lrow] = av.w;
        Bs[0][lk + 0][lrow] = bv.x;
        Bs[0][lk + 1][lrow] = bv.y;
        Bs[0][lk + 2][lrow] = bv.z;
        Bs[0][lk + 3][lrow] = bv.w;
    }
    __syncthreads();

    #pragma unroll 2
    for (int k0 = 0; k0 < Cd; k0 += 8) {
        const int buf = (k0 >> 3) & 1;
        const bool more = (k0 + 8 < Cd);

        float4 av_n, bv_n;
        if (more) {
            av_n = *(const float4*)(Ap + k0 + 8);
            bv_n = *(const float4*)(Bp + k0 + 8);
        }

        #pragma unroll
        for (int kk = 0; kk < 8; kk++) {
            const float4 alo = *(const float4*)&As[buf][kk][ty * 8];
            const float4 ahi = *(const float4*)&As[buf][kk][ty * 8 + 4];
            const ulonglong2 bL = *(const ulonglong2*)&Bs[buf][kk][tx * 4];
            const ulonglong2 bH = *(const ulonglong2*)&Bs[buf][kk][64 + tx * 4];

            unsigned long long a2[8];
            DUP2(a2[0], alo.x); DUP2(a2[1], alo.y);
            DUP2(a2[2], alo.z); DUP2(a2[3], alo.w);
            DUP2(a2[4], ahi.x); DUP2(a2[5], ahi.y);
            DUP2(a2[6], ahi.z); DUP2(a2[7], ahi.w);

            #pragma unroll
            for (int i = 0; i < 8; i++) {
                FMA2(acc[i][0], a2[i], bL.x);
                FMA2(acc[i][1], a2[i], bL.y);
                FMA2(acc[i][2], a2[i], bH.x);
                FMA2(acc[i][3], a2[i], bH.y);
            }
        }

        if (more) {
            const int nb = buf ^ 1;
            As[nb][lk + 0][lrow] = av_n.x;
            As[nb][lk + 1][lrow] = av_n.y;
            As[nb][lk + 2][lrow] = av_n.z;
            As[nb][lk + 3][lrow] = av_n.w;
            Bs[nb][lk + 0][lrow] = bv_n.x;
            Bs[nb][lk + 1][lrow] = bv_n.y;
            Bs[nb][lk + 2][lrow] = bv_n.z;
            Bs[nb][lk + 3][lrow] = bv_n.w;
        }
        __syncthreads();
    }

    // ---- epilogue: mask, distances, per-p reduction ----
    #pragma unroll
    for (int i = 0; i < 8; i++) {
        const int p = ty * 8 + i;
        const float px = s1x[p], py = s1y[p];
        int   cnt  = 0;
        float dsum = 0.0f;
        float dmin = 3.402823466e38f;
        #pragma unroll
        for (int j = 0; j < 4; j++) {
            unsigned lo_u, hi_u;
            asm("mov.b64 {%0, %1}, %2;" : "=r"(lo_u), "=r"(hi_u) : "l"(acc[i][j]));
            const float dlo = __uint_as_float(lo_u);
            const float dhi = __uint_as_float(hi_u);
            const int n0 = (j < 2) ? (tx * 4 + 2 * j) : (64 + tx * 4 + 2 * (j - 2));
            if (dlo >= 0.0f) {
                const float dx = px - s2x[n0], dy = py - s2y[n0];
                const float d = sqrtf(dx * dx + dy * dy);
                cnt++; dsum += d; dmin = fminf(dmin, d);
            }
            if (dhi >= 0.0f) {
                const float dx = px - s2x[n0 + 1], dy = py - s2y[n0 + 1];
                const float d = sqrtf(dx * dx + dy * dy);
                cnt++; dsum += d; dmin = fminf(dmin, d);
            }
        }
        #pragma unroll
        for (int off = 1; off < 16; off <<= 1) {
            cnt  += __shfl_xor_sync(0xffffffffu, cnt,  off);
            dsum += __shfl_xor_sync(0xffffffffu, dsum, off);
            dmin  = fminf(dmin, __shfl_xor_sync(0xffffffffu, dmin, off));
        }
        if (tx == 0) {
            const int idx = (o * NP + p) * NTILES + nt;
            g_cnt[idx]  = cnt;
            g_dsum[idx] = dsum;
            g_dmin[idx] = dmin;
        }
    }
}

// =================================================================
// Kernel 4: combine tile partials -> chamfer costs -> scalar loss.
// =================================================================
__global__ __launch_bounds__(512)
void final_kernel(float* __restrict__ out) {
    __shared__ float red[512];
    const int tid = threadIdx.x;

    float local = 0.0f;
    #pragma unroll
    for (int it = 0; it < (NOBJ * NP) / 512; it++) {
        const int cell = it * 512 + tid;
        const int idx0 = cell * NTILES;
        int   cnt  = 0;
        float dsum = 0.0f;
        float dmin = 3.402823466e38f;
        #pragma unroll
        for (int t = 0; t < NTILES; t += 4) {
            const int4   c4 = *(const int4*)  (g_cnt  + idx0 + t);
            const float4 s4 = *(const float4*)(g_dsum + idx0 + t);
            const float4 m4 = *(const float4*)(g_dmin + idx0 + t);
            cnt  += c4.x + c4.y + c4.z + c4.w;
            dsum += s4.x + s4.y + s4.z + s4.w;
            dmin  = fminf(dmin, fminf(fminf(m4.x, m4.y), fminf(m4.z, m4.w)));
        }
        if (cnt > 0)
            local += 0.5f * (dmin + dsum / (float)cnt) * g_m[cell >> 7];
    }
    red[tid] = local;
    __syncthreads();
    for (int s = 256; s > 0; s >>= 1) {
        if (tid < s) red[tid] += red[tid + s];
        __syncthreads();
    }
    if (tid == 0) out[0] = red[0] * (1.0f / (float)(NOBJ * NP));
}

// =================================================================
// kernel_launch: 5 launches, graph-capturable, no allocations.
// =================================================================
extern "C" void kernel_launch(void* const* d_in, const int* in_sizes, int n_in,
                              void* d_out, int out_size) {
    const float* ps1   = nullptr;
    const float* ps2   = nullptr;
    const float* feats = nullptr;
    const float* kp    = nullptr;
    for (int i = 0; i < n_in; i++) {
        if (in_sizes[i] == 37748736)      feats = (const float*)d_in[i];
        else if (in_sizes[i] == 65536)    ps2   = (const float*)d_in[i];
        else if (in_sizes[i] == 4096) {
            if (!ps1) ps1 = (const float*)d_in[i];
            else      kp  = (const float*)d_in[i];
        }
    }
    float* out = (float*)d_out;

    m_kernel<<<NOBJ, 256>>>(ps2);
    transpose_kernel<<<dim3(HWd / 32, Cd / 32), dim3(8, 32)>>>(feats);
    sample_kernel<<<NPTS / 8, dim3(32, 8)>>>(kp, ps2);
    gemm_mask_kernel<<<dim3(NTILES, NOBJ), 256>>>(ps1, ps2);
    final_kernel<<<1, 512>>>(out);
}

// round 13
// speedup vs baseline: 2.1627x; 1.4286x over previous
#include <cuda_runtime.h>
#include <cuda_bf16.h>
#include <cstdint>

// ---------------- problem constants ----------------
#define Wd   384
#define Hd   384
#define Cd   256
#define HWd  (Wd * Hd)          // 147456
#define NOBJ 16
#define NP   128
#define NN   2048
#define NKP  2048               // N_OBJ * N_P key points
#define NPTS (NKP + NOBJ * NN)  // 34816 total sampled points
#define NTILES 16               // 2048 / 128 n-tiles per object

// ---------------- device scratch (static: no allocations allowed) ----------------
__device__ __nv_bfloat16 g_imgTh[(size_t)HWd * Cd]; // [s][c] transposed image, bf16 (75 MB)
__device__ __nv_bfloat16 g_Fh[(size_t)NPTS * Cd];   // [pt][c] sampled features bf16 (17.8 MB)
__device__ int   g_cnt [NOBJ * NP * NTILES];
__device__ float g_dsum[NOBJ * NP * NTILES];
__device__ float g_dmin[NOBJ * NP * NTILES];
__device__ float g_m[NOBJ];

// =================================================================
// Kernel 0: m[o] = (sum(point_set_2[o]) >= 0). 16 blocks, float4.
// =================================================================
__global__ __launch_bounds__(256)
void m_kernel(const float* __restrict__ ps2) {
    __shared__ float red[8];
    const int o   = blockIdx.x;
    const int tid = threadIdx.x;
    const float4* p = (const float4*)(ps2 + (size_t)o * (NN * 2));
    float s = 0.0f;
    #pragma unroll
    for (int i = 0; i < 16; i++) {
        const float4 v = p[tid + i * 256];
        s += v.x + v.y + v.z + v.w;
    }
    #pragma unroll
    for (int off = 16; off; off >>= 1) s += __shfl_xor_sync(0xffffffffu, s, off);
    if ((tid & 31) == 0) red[tid >> 5] = s;
    __syncthreads();
    if (tid == 0) {
        float t = 0.0f;
        #pragma unroll
        for (int w = 0; w < 8; w++) t += red[w];
        g_m[o] = (t >= 0.0f) ? 1.0f : 0.0f;
    }
}

// =================================================================
// Kernel 1: transpose feats [C,H,W] -> g_imgTh [H*W, C] in bf16.
// =================================================================
__global__ void transpose_kernel(const float* __restrict__ in) {
    __shared__ float tile[32][33];
    const int bs = blockIdx.x * 32;     // s base (pixel index)
    const int bc = blockIdx.y * 32;     // c base
    const int tx = threadIdx.x;         // 0..7
    const int ty = threadIdx.y;         // 0..31

    const float4 v = *(const float4*)(in + (size_t)(bc + ty) * HWd + bs + tx * 4);
    tile[ty][tx * 4 + 0] = v.x;
    tile[ty][tx * 4 + 1] = v.y;
    tile[ty][tx * 4 + 2] = v.z;
    tile[ty][tx * 4 + 3] = v.w;
    __syncthreads();

    const float w0 = tile[tx * 4 + 0][ty];
    const float w1 = tile[tx * 4 + 1][ty];
    const float w2 = tile[tx * 4 + 2][ty];
    const float w3 = tile[tx * 4 + 3][ty];
    uint2 o;
    {
        const __nv_bfloat162 lo = __floats2bfloat162_rn(w0, w1);
        const __nv_bfloat162 hi = __floats2bfloat162_rn(w2, w3);
        o.x = *(const unsigned*)&lo;
        o.y = *(const unsigned*)&hi;
    }
    *(uint2*)(g_imgTh + (size_t)(bs + ty) * Cd + bc + tx * 4) = o;
}

// =================================================================
// Kernel 2: bilinear grid-sample from bf16 image -> bf16 features.
// Block = 8 points x 32 lanes (8 channels each).
// =================================================================
__global__ __launch_bounds__(256)
void sample_kernel(const float* __restrict__ kp,
                   const float* __restrict__ ps2) {
    const int lane = threadIdx.x;                     // 0..31, 8 channels each
    const int pt   = blockIdx.x * 8 + threadIdx.y;    // 0..34815

    const float* src = (pt < NKP) ? (kp + (size_t)pt * 2)
                                  : (ps2 + (size_t)(pt - NKP) * 2);
    const float px = src[0];
    const float py = src[1];

    // exact reference math (grid_sample, align_corners=False)
    const float gx = 2.0f * (px * (1.0f / 384.0f)) - 1.0f;
    const float gy = 2.0f * (py * (1.0f / 384.0f)) - 1.0f;
    const float x  = ((gx + 1.0f) * 384.0f - 1.0f) * 0.5f;
    const float y  = ((gy + 1.0f) * 384.0f - 1.0f) * 0.5f;

    const float x0f = floorf(x), y0f = floorf(y);
    const float wx1 = x - x0f,   wy1 = y - y0f;
    const float wx0 = 1.0f - wx1, wy0 = 1.0f - wy1;
    const int x0 = (int)x0f, y0 = (int)y0f;
    const int x1 = x0 + 1,   y1 = y0 + 1;

    const float vx0 = (x0 >= 0 && x0 < Wd) ? 1.0f : 0.0f;
    const float vx1 = (x1 >= 0 && x1 < Wd) ? 1.0f : 0.0f;
    const float vy0 = (y0 >= 0 && y0 < Hd) ? 1.0f : 0.0f;
    const float vy1 = (y1 >= 0 && y1 < Hd) ? 1.0f : 0.0f;

    const float w00 = wx0 * wy0 * vx0 * vy0;
    const float w10 = wx1 * wy0 * vx1 * vy0;
    const float w01 = wx0 * wy1 * vx0 * vy1;
    const float w11 = wx1 * wy1 * vx1 * vy1;

    const int xc0 = min(max(x0, 0), Wd - 1);
    const int xc1 = min(max(x1, 0), Wd - 1);
    const int yc0 = min(max(y0, 0), Hd - 1);
    const int yc1 = min(max(y1, 0), Hd - 1);

    const size_t coff = (size_t)lane * 8;
    const uint4 r00 = *(const uint4*)(g_imgTh + ((size_t)(yc0 * Wd + xc0)) * Cd + coff);
    const uint4 r10 = *(const uint4*)(g_imgTh + ((size_t)(yc0 * Wd + xc1)) * Cd + coff);
    const uint4 r01 = *(const uint4*)(g_imgTh + ((size_t)(yc1 * Wd + xc0)) * Cd + coff);
    const uint4 r11 = *(const uint4*)(g_imgTh + ((size_t)(yc1 * Wd + xc1)) * Cd + coff);

    uint4 o4;
    #pragma unroll
    for (int q = 0; q < 4; q++) {
        const unsigned u00 = (&r00.x)[q];
        const unsigned u10 = (&r10.x)[q];
        const unsigned u01 = (&r01.x)[q];
        const unsigned u11 = (&r11.x)[q];
        const float2 f00 = __bfloat1622float2(*(const __nv_bfloat162*)&u00);
        const float2 f10 = __bfloat1622float2(*(const __nv_bfloat162*)&u10);
        const float2 f01 = __bfloat1622float2(*(const __nv_bfloat162*)&u01);
        const float2 f11 = __bfloat1622float2(*(const __nv_bfloat162*)&u11);
        const float oa = w00 * f00.x + w10 * f10.x + w01 * f01.x + w11 * f11.x;
        const float ob = w00 * f00.y + w10 * f10.y + w01 * f01.y + w11 * f11.y;
        const __nv_bfloat162 pk = __floats2bfloat162_rn(oa, ob);
        (&o4.x)[q] = *(const unsigned*)&pk;
    }

    *(uint4*)(g_Fh + (size_t)pt * Cd + coff) = o4;
}

// =================================================================
// Kernel 3: HMMA (mma.sync m16n8k16 bf16) GEMM sign + distance +
// masked reduction. compute_80-baseline instructions only (the
// harness builds PTX at compute_103, which rejects tcgen05).
// CTA = (nt, o): D[128p x 128n] = f1 @ f2^T, K=256 in 4 chunks of 64.
// 8 warps as 2(m) x 4(n); warp tile 64x32 (4 mtiles x 4 ntiles).
// A,B chunks in SW128-xor-swizzled smem; ldmatrix.x4 conflict-free.
// Epilogue: per-lane mask/dist on acc frags, quad-shfl n-reduction,
// smem combine across the 4 n-warps, one partial per (p, nt).
// =================================================================
__device__ __forceinline__ uint32_t smem_u32(const void* p) {
    uint32_t a;
    asm("{ .reg .u64 t; cvta.to.shared.u64 t, %1; cvt.u32.u64 %0, t; }" : "=r"(a) : "l"(p));
    return a;
}
#define LDSM_X4(r0, r1, r2, r3, addr) \
    asm volatile("ldmatrix.sync.aligned.m8n8.x4.shared.b16 {%0,%1,%2,%3}, [%4];" \
                 : "=r"(r0), "=r"(r1), "=r"(r2), "=r"(r3) : "r"(addr))
#define MMA16816(d, a, b) \
    asm volatile("mma.sync.aligned.m16n8k16.row.col.f32.bf16.bf16.f32 " \
                 "{%0,%1,%2,%3}, {%4,%5,%6,%7}, {%8,%9}, {%0,%1,%2,%3};" \
                 : "+f"((d)[0]), "+f"((d)[1]), "+f"((d)[2]), "+f"((d)[3]) \
                 : "r"((a)[0]), "r"((a)[1]), "r"((a)[2]), "r"((a)[3]), \
                   "r"((b)[0]), "r"((b)[1]))

__global__ __launch_bounds__(256, 2)
void gemm_mma_kernel(const float* __restrict__ ps1,
                     const float* __restrict__ ps2) {
    __shared__ __align__(16) char sA[16384];   // chunk: [128 rows][64 bf16], SW128 swizzled
    __shared__ __align__(16) char sB[16384];
    __shared__ float s1x[128], s1y[128], s2x[128], s2y[128];
    __shared__ float r_cnt[4][128], r_sum[4][128], r_min[4][128];

    const int o    = blockIdx.y;
    const int nt   = blockIdx.x;
    const int tid  = threadIdx.x;
    const int wid  = tid >> 5;
    const int lane = tid & 31;
    const int warp_m = wid >> 2;          // 0..1
    const int warp_n = wid & 3;           // 0..3
    const int m_base = warp_m * 64;
    const int n_base = warp_n * 32;

    const uint32_t sAb = smem_u32(sA);
    const uint32_t sBb = smem_u32(sB);

    if (tid < 128) {
        const size_t i1 = ((size_t)o * NP + tid) * 2;
        s1x[tid] = ps1[i1];
        s1y[tid] = ps1[i1 + 1];
        const size_t i2 = ((size_t)o * NN + nt * 128 + tid) * 2;
        s2x[tid] = ps2[i2];
        s2y[tid] = ps2[i2 + 1];
    }

    const char* gA = (const char*)(g_Fh + (size_t)(o * 128) * Cd);            // [128][512B]
    const char* gB = (const char*)(g_Fh + (size_t)(NKP + o * NN + nt * 128) * Cd);

    float acc[4][4][4];
    #pragma unroll
    for (int mt = 0; mt < 4; mt++)
        #pragma unroll
        for (int nn = 0; nn < 4; nn++)
            #pragma unroll
            for (int q = 0; q < 4; q++) acc[mt][nn][q] = 0.0f;

    // per-lane ldmatrix row/granule bases (see fragment layout notes)
    const int rowA = m_base + (lane & 7) + (((lane >> 3) & 1) << 3);  // + mt*16
    const int gA_l = (lane >> 4);                                     // + ks*2
    const int rowB = n_base + (lane & 7) + ((lane >> 4) << 3);        // + half*16
    const int gB_l = ((lane >> 3) & 1);                               // + ks*2

    #pragma unroll 1
    for (int chunk = 0; chunk < 4; chunk++) {
        // ---- stage chunk [128][64]bf16 with SW128 xor swizzle ----
        #pragma unroll
        for (int j = 0; j < 4; j++) {
            const int idx = j * 256 + tid;        // 0..1023 granules
            const int row = idx >> 3;
            const int g   = idx & 7;
            const uint32_t off = (row << 7) + (g << 4);
            const uint32_t sw  = off ^ ((off >> 3) & 0x70);
            *(uint4*)(sA + sw) = *(const uint4*)(gA + row * 512 + chunk * 128 + g * 16);
            *(uint4*)(sB + sw) = *(const uint4*)(gB + row * 512 + chunk * 128 + g * 16);
        }
        __syncthreads();

        #pragma unroll
        for (int ks = 0; ks < 4; ks++) {          // k16 steps within chunk
            uint32_t afr[4][4], bfr[4][2];
            // A fragments: 4 ldmatrix.x4 (one per mtile)
            #pragma unroll
            for (int mt = 0; mt < 4; mt++) {
                const int row = rowA + mt * 16;
                const int g   = ks * 2 + gA_l;
                const uint32_t off = (row << 7) + (g << 4);
                const uint32_t sw  = off ^ ((off >> 3) & 0x70);
                LDSM_X4(afr[mt][0], afr[mt][1], afr[mt][2], afr[mt][3], sAb + sw);
            }
            // B fragments: 2 ldmatrix.x4 (each covers 2 ntiles)
            #pragma unroll
            for (int h = 0; h < 2; h++) {
                const int row = rowB + h * 16;
                const int g   = ks * 2 + gB_l;
                const uint32_t off = (row << 7) + (g << 4);
                const uint32_t sw  = off ^ ((off >> 3) & 0x70);
                LDSM_X4(bfr[h * 2][0], bfr[h * 2][1],
                        bfr[h * 2 + 1][0], bfr[h * 2 + 1][1], sBb + sw);
            }
            #pragma unroll
            for (int mt = 0; mt < 4; mt++)
                #pragma unroll
                for (int nn = 0; nn < 4; nn++)
                    MMA16816(acc[mt][nn], afr[mt], bfr[nn]);
        }
        __syncthreads();   // buffers reused next chunk
    }

    // ---- epilogue: mask + distance on fragments, quad-shfl n-reduce ----
    // acc[mt][nn]: d0,d1 -> row lane/4,      cols 2(lane%4), +1
    //              d2,d3 -> row lane/4 + 8,  same cols
    #pragma unroll
    for (int mt = 0; mt < 4; mt++) {
        #pragma unroll
        for (int r01 = 0; r01 < 2; r01++) {
            const int p = m_base + mt * 16 + (lane >> 2) + r01 * 8;
            const float px = s1x[p], py = s1y[p];
            float cnt = 0.0f, ds = 0.0f, dm = 3.402823466e38f;
            #pragma unroll
            for (int nn = 0; nn < 4; nn++) {
                const int n = n_base + nn * 8 + 2 * (lane & 3);
                const float c0 = acc[mt][nn][r01 * 2 + 0];
                const float c1 = acc[mt][nn][r01 * 2 + 1];
                if (c0 >= 0.0f) {
                    const float dx = px - s2x[n], dy = py - s2y[n];
                    const float d = sqrtf(dx * dx + dy * dy);
                    cnt += 1.0f; ds += d; dm = fminf(dm, d);
                }
                if (c1 >= 0.0f) {
                    const float dx = px - s2x[n + 1], dy = py - s2y[n + 1];
                    const float d = sqrtf(dx * dx + dy * dy);
                    cnt += 1.0f; ds += d; dm = fminf(dm, d);
                }
            }
            // reduce over the 4 lanes of the quad (same p, different n)
            #pragma unroll
            for (int off = 1; off < 4; off <<= 1) {
                cnt += __shfl_xor_sync(0xffffffffu, cnt, off);
                ds  += __shfl_xor_sync(0xffffffffu, ds,  off);
                dm   = fminf(dm, __shfl_xor_sync(0xffffffffu, dm, off));
            }
            if ((lane & 3) == 0) {
                r_cnt[warp_n][p] = cnt;
                r_sum[warp_n][p] = ds;
                r_min[warp_n][p] = dm;
            }
        }
    }
    __syncthreads();

    if (tid < 128) {
        const int p = tid;
        float cnt = 0.0f, ds = 0.0f, dm = 3.402823466e38f;
        #pragma unroll
        for (int w = 0; w < 4; w++) {
            cnt += r_cnt[w][p];
            ds  += r_sum[w][p];
            dm   = fminf(dm, r_min[w][p]);
        }
        const int idx = (o * NP + p) * NTILES + nt;
        g_cnt[idx]  = (int)cnt;
        g_dsum[idx] = ds;
        g_dmin[idx] = dm;
    }
}

// =================================================================
// Kernel 4: combine tile partials -> chamfer costs -> scalar loss.
// =================================================================
__global__ __launch_bounds__(512)
void final_kernel(float* __restrict__ out) {
    __shared__ float red[512];
    const int tid = threadIdx.x;

    float local = 0.0f;
    #pragma unroll
    for (int it = 0; it < (NOBJ * NP) / 512; it++) {
        const int cell = it * 512 + tid;
        const int idx0 = cell * NTILES;
        int   cnt  = 0;
        float dsum = 0.0f;
        float dmin = 3.402823466e38f;
        #pragma unroll
        for (int t = 0; t < NTILES; t += 4) {
            const int4   c4 = *(const int4*)  (g_cnt  + idx0 + t);
            const float4 s4 = *(const float4*)(g_dsum + idx0 + t);
            const float4 m4 = *(const float4*)(g_dmin + idx0 + t);
            cnt  += c4.x + c4.y + c4.z + c4.w;
            dsum += s4.x + s4.y + s4.z + s4.w;
            dmin  = fminf(dmin, fminf(fminf(m4.x, m4.y), fminf(m4.z, m4.w)));
        }
        if (cnt > 0)
            local += 0.5f * (dmin + dsum / (float)cnt) * g_m[cell >> 7];
    }
    red[tid] = local;
    __syncthreads();
    for (int s = 256; s > 0; s >>= 1) {
        if (tid < s) red[tid] += red[tid + s];
        __syncthreads();
    }
    if (tid == 0) out[0] = red[0] * (1.0f / (float)(NOBJ * NP));
}

// =================================================================
// kernel_launch: 5 launches, graph-capturable, no allocations,
// no static state.
// =================================================================
extern "C" void kernel_launch(void* const* d_in, const int* in_sizes, int n_in,
                              void* d_out, int out_size) {
    const float* ps1   = nullptr;
    const float* ps2   = nullptr;
    const float* feats = nullptr;
    const float* kp    = nullptr;
    for (int i = 0; i < n_in; i++) {
        if (in_sizes[i] == 37748736)      feats = (const float*)d_in[i];
        else if (in_sizes[i] == 65536)    ps2   = (const float*)d_in[i];
        else if (in_sizes[i] == 4096) {
            if (!ps1) ps1 = (const float*)d_in[i];
            else      kp  = (const float*)d_in[i];
        }
    }
    float* out = (float*)d_out;

    m_kernel<<<NOBJ, 256>>>(ps2);
    transpose_kernel<<<dim3(HWd / 32, Cd / 32), dim3(8, 32)>>>(feats);
    sample_kernel<<<NPTS / 8, dim3(32, 8)>>>(kp, ps2);
    gemm_mma_kernel<<<dim3(NTILES, NOBJ), 256>>>(ps1, ps2);
    final_kernel<<<1, 512>>>(out);
}

// round 14
// speedup vs baseline: 2.2160x; 1.0246x over previous
#include <cuda_runtime.h>
#include <cuda_bf16.h>
#include <cstdint>

// ---------------- problem constants ----------------
#define Wd   384
#define Hd   384
#define Cd   256
#define HWd  (Wd * Hd)          // 147456
#define NOBJ 16
#define NP   128
#define NN   2048
#define NKP  2048               // N_OBJ * N_P key points
#define NPTS (NKP + NOBJ * NN)  // 34816 total sampled points
#define NTILES 16               // 2048 / 128 n-tiles per object

// ---------------- device scratch (static: no allocations allowed) ----------------
__device__ __nv_bfloat16 g_imgTh[(size_t)HWd * Cd]; // [s][c] transposed image, bf16 (75 MB)
__device__ __nv_bfloat16 g_Fh[(size_t)NPTS * Cd];   // [pt][c] sampled features bf16 (17.8 MB)
__device__ int   g_cnt [NOBJ * NP * NTILES];
__device__ float g_dsum[NOBJ * NP * NTILES];
__device__ float g_dmin[NOBJ * NP * NTILES];
__device__ float g_m[NOBJ];

// =================================================================
// Kernel 0: m[o] = (sum(point_set_2[o]) >= 0). 16 blocks, float4.
// =================================================================
__global__ __launch_bounds__(256)
void m_kernel(const float* __restrict__ ps2) {
    __shared__ float red[8];
    const int o   = blockIdx.x;
    const int tid = threadIdx.x;
    const float4* p = (const float4*)(ps2 + (size_t)o * (NN * 2));
    float s = 0.0f;
    #pragma unroll
    for (int i = 0; i < 16; i++) {
        const float4 v = p[tid + i * 256];
        s += v.x + v.y + v.z + v.w;
    }
    #pragma unroll
    for (int off = 16; off; off >>= 1) s += __shfl_xor_sync(0xffffffffu, s, off);
    if ((tid & 31) == 0) red[tid >> 5] = s;
    __syncthreads();
    if (tid == 0) {
        float t = 0.0f;
        #pragma unroll
        for (int w = 0; w < 8; w++) t += red[w];
        g_m[o] = (t >= 0.0f) ? 1.0f : 0.0f;
    }
}

// =================================================================
// Kernel 1: transpose feats [C,H,W] -> g_imgTh [H*W, C] in bf16.
// =================================================================
__global__ void transpose_kernel(const float* __restrict__ in) {
    __shared__ float tile[32][33];
    const int bs = blockIdx.x * 32;     // s base (pixel index)
    const int bc = blockIdx.y * 32;     // c base
    const int tx = threadIdx.x;         // 0..7
    const int ty = threadIdx.y;         // 0..31

    const float4 v = *(const float4*)(in + (size_t)(bc + ty) * HWd + bs + tx * 4);
    tile[ty][tx * 4 + 0] = v.x;
    tile[ty][tx * 4 + 1] = v.y;
    tile[ty][tx * 4 + 2] = v.z;
    tile[ty][tx * 4 + 3] = v.w;
    __syncthreads();

    const float w0 = tile[tx * 4 + 0][ty];
    const float w1 = tile[tx * 4 + 1][ty];
    const float w2 = tile[tx * 4 + 2][ty];
    const float w3 = tile[tx * 4 + 3][ty];
    uint2 o;
    {
        const __nv_bfloat162 lo = __floats2bfloat162_rn(w0, w1);
        const __nv_bfloat162 hi = __floats2bfloat162_rn(w2, w3);
        o.x = *(const unsigned*)&lo;
        o.y = *(const unsigned*)&hi;
    }
    *(uint2*)(g_imgTh + (size_t)(bs + ty) * Cd + bc + tx * 4) = o;
}

// =================================================================
// Kernel 2: bilinear grid-sample from bf16 image -> bf16 features.
// Block = 8 points x 32 lanes (8 channels each).
// =================================================================
__global__ __launch_bounds__(256)
void sample_kernel(const float* __restrict__ kp,
                   const float* __restrict__ ps2) {
    const int lane = threadIdx.x;                     // 0..31, 8 channels each
    const int pt   = blockIdx.x * 8 + threadIdx.y;    // 0..34815

    const float* src = (pt < NKP) ? (kp + (size_t)pt * 2)
                                  : (ps2 + (size_t)(pt - NKP) * 2);
    const float px = src[0];
    const float py = src[1];

    // exact reference math (grid_sample, align_corners=False)
    const float gx = 2.0f * (px * (1.0f / 384.0f)) - 1.0f;
    const float gy = 2.0f * (py * (1.0f / 384.0f)) - 1.0f;
    const float x  = ((gx + 1.0f) * 384.0f - 1.0f) * 0.5f;
    const float y  = ((gy + 1.0f) * 384.0f - 1.0f) * 0.5f;

    const float x0f = floorf(x), y0f = floorf(y);
    const float wx1 = x - x0f,   wy1 = y - y0f;
    const float wx0 = 1.0f - wx1, wy0 = 1.0f - wy1;
    const int x0 = (int)x0f, y0 = (int)y0f;
    const int x1 = x0 + 1,   y1 = y0 + 1;

    const float vx0 = (x0 >= 0 && x0 < Wd) ? 1.0f : 0.0f;
    const float vx1 = (x1 >= 0 && x1 < Wd) ? 1.0f : 0.0f;
    const float vy0 = (y0 >= 0 && y0 < Hd) ? 1.0f : 0.0f;
    const float vy1 = (y1 >= 0 && y1 < Hd) ? 1.0f : 0.0f;

    const float w00 = wx0 * wy0 * vx0 * vy0;
    const float w10 = wx1 * wy0 * vx1 * vy0;
    const float w01 = wx0 * wy1 * vx0 * vy1;
    const float w11 = wx1 * wy1 * vx1 * vy1;

    const int xc0 = min(max(x0, 0), Wd - 1);
    const int xc1 = min(max(x1, 0), Wd - 1);
    const int yc0 = min(max(y0, 0), Hd - 1);
    const int yc1 = min(max(y1, 0), Hd - 1);

    const size_t coff = (size_t)lane * 8;
    const uint4 r00 = *(const uint4*)(g_imgTh + ((size_t)(yc0 * Wd + xc0)) * Cd + coff);
    const uint4 r10 = *(const uint4*)(g_imgTh + ((size_t)(yc0 * Wd + xc1)) * Cd + coff);
    const uint4 r01 = *(const uint4*)(g_imgTh + ((size_t)(yc1 * Wd + xc0)) * Cd + coff);
    const uint4 r11 = *(const uint4*)(g_imgTh + ((size_t)(yc1 * Wd + xc1)) * Cd + coff);

    uint4 o4;
    #pragma unroll
    for (int q = 0; q < 4; q++) {
        const unsigned u00 = (&r00.x)[q];
        const unsigned u10 = (&r10.x)[q];
        const unsigned u01 = (&r01.x)[q];
        const unsigned u11 = (&r11.x)[q];
        const float2 f00 = __bfloat1622float2(*(const __nv_bfloat162*)&u00);
        const float2 f10 = __bfloat1622float2(*(const __nv_bfloat162*)&u10);
        const float2 f01 = __bfloat1622float2(*(const __nv_bfloat162*)&u01);
        const float2 f11 = __bfloat1622float2(*(const __nv_bfloat162*)&u11);
        const float oa = w00 * f00.x + w10 * f10.x + w01 * f01.x + w11 * f11.x;
        const float ob = w00 * f00.y + w10 * f10.y + w01 * f01.y + w11 * f11.y;
        const __nv_bfloat162 pk = __floats2bfloat162_rn(oa, ob);
        (&o4.x)[q] = *(const unsigned*)&pk;
    }

    *(uint4*)(g_Fh + (size_t)pt * Cd + coff) = o4;
}

// =================================================================
// Kernel 3: HMMA (mma.sync m16n8k16 bf16) GEMM sign + distance +
// masked reduction — now with cp.async DOUBLE-BUFFERED K-chunks.
// CTA = (nt, o): D[128p x 128n] = f1 @ f2^T, K=256 in 4 chunks of 64.
// Chunk c+1 streams into the alternate smem buffer (cp.async.cg)
// while chunk c computes; wait_group + barrier per chunk.
// Dynamic smem 72 KB (2 CTAs/SM resident).
// =================================================================
__device__ __forceinline__ uint32_t smem_u32(const void* p) {
    uint32_t a;
    asm("{ .reg .u64 t; cvta.to.shared.u64 t, %1; cvt.u32.u64 %0, t; }" : "=r"(a) : "l"(p));
    return a;
}
#define LDSM_X4(r0, r1, r2, r3, addr) \
    asm volatile("ldmatrix.sync.aligned.m8n8.x4.shared.b16 {%0,%1,%2,%3}, [%4];" \
                 : "=r"(r0), "=r"(r1), "=r"(r2), "=r"(r3) : "r"(addr))
#define MMA16816(d, a, b) \
    asm volatile("mma.sync.aligned.m16n8k16.row.col.f32.bf16.bf16.f32 " \
                 "{%0,%1,%2,%3}, {%4,%5,%6,%7}, {%8,%9}, {%0,%1,%2,%3};" \
                 : "+f"((d)[0]), "+f"((d)[1]), "+f"((d)[2]), "+f"((d)[3]) \
                 : "r"((a)[0]), "r"((a)[1]), "r"((a)[2]), "r"((a)[3]), \
                   "r"((b)[0]), "r"((b)[1]))
#define CP_ASYNC16(dst, src) \
    asm volatile("cp.async.cg.shared.global [%0], [%1], 16;" :: "r"(dst), "l"(src))
#define CP_COMMIT() asm volatile("cp.async.commit_group;" ::: "memory")
#define CP_WAIT(n)  asm volatile("cp.async.wait_group %0;" :: "n"(n) : "memory")

// dynamic smem layout (bytes)
#define GSM_A0   0
#define GSM_A1   16384
#define GSM_B0   32768
#define GSM_B1   49152
#define GSM_PTS  65536                       // s1x,s1y,s2x,s2y: 4*512
#define GSM_RED  (GSM_PTS + 2048)            // r_cnt/r_sum/r_min: 3*4*128*4
#define GSM_TOTAL (GSM_RED + 6144)           // 73728 B

__global__ __launch_bounds__(256, 2)
void gemm_mma_kernel(const float* __restrict__ ps1,
                     const float* __restrict__ ps2) {
    extern __shared__ __align__(16) char sm[];
    const uint32_t smb = smem_u32(sm);

    const int o    = blockIdx.y;
    const int nt   = blockIdx.x;
    const int tid  = threadIdx.x;
    const int wid  = tid >> 5;
    const int lane = tid & 31;
    const int warp_m = wid >> 2;          // 0..1
    const int warp_n = wid & 3;           // 0..3
    const int m_base = warp_m * 64;
    const int n_base = warp_n * 32;

    float* s1x = (float*)(sm + GSM_PTS);
    float* s1y = s1x + 128;
    float* s2x = s1y + 128;
    float* s2y = s2x + 128;
    float* r_cnt = (float*)(sm + GSM_RED);          // [4][128]
    float* r_sum = r_cnt + 4 * 128;
    float* r_min = r_sum + 4 * 128;

    if (tid < 128) {
        const size_t i1 = ((size_t)o * NP + tid) * 2;
        s1x[tid] = ps1[i1];
        s1y[tid] = ps1[i1 + 1];
        const size_t i2 = ((size_t)o * NN + nt * 128 + tid) * 2;
        s2x[tid] = ps2[i2];
        s2y[tid] = ps2[i2 + 1];
    }

    const char* gA = (const char*)(g_Fh + (size_t)(o * 128) * Cd);            // [128][512B]
    const char* gB = (const char*)(g_Fh + (size_t)(NKP + o * NN + nt * 128) * Cd);

    float acc[4][4][4];
    #pragma unroll
    for (int mt = 0; mt < 4; mt++)
        #pragma unroll
        for (int nn = 0; nn < 4; nn++)
            #pragma unroll
            for (int q = 0; q < 4; q++) acc[mt][nn][q] = 0.0f;

    // per-lane ldmatrix row/granule bases
    const int rowA = m_base + (lane & 7) + (((lane >> 3) & 1) << 3);  // + mt*16
    const int gA_l = (lane >> 4);                                     // + ks*2
    const int rowB = n_base + (lane & 7) + ((lane >> 4) << 3);        // + half*16
    const int gB_l = ((lane >> 3) & 1);                               // + ks*2

    // precomputed per-thread staging slots (4 granules each)
    uint32_t st_sw[4];
    uint32_t st_go[4];
    #pragma unroll
    for (int j = 0; j < 4; j++) {
        const int idx = j * 256 + tid;        // 0..1023 granules
        const int row = idx >> 3;
        const int g   = idx & 7;
        const uint32_t off = (row << 7) + (g << 4);
        st_sw[j] = off ^ ((off >> 3) & 0x70);
        st_go[j] = row * 512 + g * 16;        // + chunk*128
    }

    // ---- prologue: stage chunk 0 into buffer 0 ----
    #pragma unroll
    for (int j = 0; j < 4; j++) {
        CP_ASYNC16(smb + GSM_A0 + st_sw[j], gA + st_go[j]);
        CP_ASYNC16(smb + GSM_B0 + st_sw[j], gB + st_go[j]);
    }
    CP_COMMIT();

    #pragma unroll
    for (int chunk = 0; chunk < 4; chunk++) {
        const uint32_t bA = smb + ((chunk & 1) ? GSM_A1 : GSM_A0);
        const uint32_t bB = smb + ((chunk & 1) ? GSM_B1 : GSM_B0);

        // issue next chunk into the other buffer (overlaps with compute)
        if (chunk < 3) {
            const uint32_t nA = smb + ((chunk & 1) ? GSM_A0 : GSM_A1);
            const uint32_t nB = smb + ((chunk & 1) ? GSM_B0 : GSM_B1);
            const uint32_t co = (chunk + 1) * 128;
            #pragma unroll
            for (int j = 0; j < 4; j++) {
                CP_ASYNC16(nA + st_sw[j], gA + st_go[j] + co);
                CP_ASYNC16(nB + st_sw[j], gB + st_go[j] + co);
            }
            CP_COMMIT();
            CP_WAIT(1);            // current chunk's group complete
        } else {
            CP_WAIT(0);
        }
        __syncthreads();

        #pragma unroll
        for (int ks = 0; ks < 4; ks++) {          // k16 steps within chunk
            uint32_t afr[4][4], bfr[4][2];
            #pragma unroll
            for (int mt = 0; mt < 4; mt++) {
                const int row = rowA + mt * 16;
                const int g   = ks * 2 + gA_l;
                const uint32_t off = (row << 7) + (g << 4);
                const uint32_t sw  = off ^ ((off >> 3) & 0x70);
                LDSM_X4(afr[mt][0], afr[mt][1], afr[mt][2], afr[mt][3], bA + sw);
            }
            #pragma unroll
            for (int h = 0; h < 2; h++) {
                const int row = rowB + h * 16;
                const int g   = ks * 2 + gB_l;
                const uint32_t off = (row << 7) + (g << 4);
                const uint32_t sw  = off ^ ((off >> 3) & 0x70);
                LDSM_X4(bfr[h * 2][0], bfr[h * 2][1],
                        bfr[h * 2 + 1][0], bfr[h * 2 + 1][1], bB + sw);
            }
            #pragma unroll
            for (int mt = 0; mt < 4; mt++)
                #pragma unroll
                for (int nn = 0; nn < 4; nn++)
                    MMA16816(acc[mt][nn], afr[mt], bfr[nn]);
        }
        __syncthreads();   // buffer reused by the chunk+2 issue
    }

    // ---- epilogue: mask + distance on fragments, quad-shfl n-reduce ----
    #pragma unroll
    for (int mt = 0; mt < 4; mt++) {
        #pragma unroll
        for (int r01 = 0; r01 < 2; r01++) {
            const int p = m_base + mt * 16 + (lane >> 2) + r01 * 8;
            const float px = s1x[p], py = s1y[p];
            float cnt = 0.0f, ds = 0.0f, dm = 3.402823466e38f;
            #pragma unroll
            for (int nn = 0; nn < 4; nn++) {
                const int n = n_base + nn * 8 + 2 * (lane & 3);
                const float c0 = acc[mt][nn][r01 * 2 + 0];
                const float c1 = acc[mt][nn][r01 * 2 + 1];
                if (c0 >= 0.0f) {
                    const float dx = px - s2x[n], dy = py - s2y[n];
                    const float d = sqrtf(dx * dx + dy * dy);
                    cnt += 1.0f; ds += d; dm = fminf(dm, d);
                }
                if (c1 >= 0.0f) {
                    const float dx = px - s2x[n + 1], dy = py - s2y[n + 1];
                    const float d = sqrtf(dx * dx + dy * dy);
                    cnt += 1.0f; ds += d; dm = fminf(dm, d);
                }
            }
            #pragma unroll
            for (int off = 1; off < 4; off <<= 1) {
                cnt += __shfl_xor_sync(0xffffffffu, cnt, off);
                ds  += __shfl_xor_sync(0xffffffffu, ds,  off);
                dm   = fminf(dm, __shfl_xor_sync(0xffffffffu, dm, off));
            }
            if ((lane & 3) == 0) {
                r_cnt[warp_n * 128 + p] = cnt;
                r_sum[warp_n * 128 + p] = ds;
                r_min[warp_n * 128 + p] = dm;
            }
        }
    }
    __syncthreads();

    if (tid < 128) {
        const int p = tid;
        float cnt = 0.0f, ds = 0.0f, dm = 3.402823466e38f;
        #pragma unroll
        for (int w = 0; w < 4; w++) {
            cnt += r_cnt[w * 128 + p];
            ds  += r_sum[w * 128 + p];
            dm   = fminf(dm, r_min[w * 128 + p]);
        }
        const int idx = (o * NP + p) * NTILES + nt;
        g_cnt[idx]  = (int)cnt;
        g_dsum[idx] = ds;
        g_dmin[idx] = dm;
    }
}

// =================================================================
// Kernel 4: combine tile partials -> chamfer costs -> scalar loss.
// =================================================================
__global__ __launch_bounds__(512)
void final_kernel(float* __restrict__ out) {
    __shared__ float red[512];
    const int tid = threadIdx.x;

    float local = 0.0f;
    #pragma unroll
    for (int it = 0; it < (NOBJ * NP) / 512; it++) {
        const int cell = it * 512 + tid;
        const int idx0 = cell * NTILES;
        int   cnt  = 0;
        float dsum = 0.0f;
        float dmin = 3.402823466e38f;
        #pragma unroll
        for (int t = 0; t < NTILES; t += 4) {
            const int4   c4 = *(const int4*)  (g_cnt  + idx0 + t);
            const float4 s4 = *(const float4*)(g_dsum + idx0 + t);
            const float4 m4 = *(const float4*)(g_dmin + idx0 + t);
            cnt  += c4.x + c4.y + c4.z + c4.w;
            dsum += s4.x + s4.y + s4.z + s4.w;
            dmin  = fminf(dmin, fminf(fminf(m4.x, m4.y), fminf(m4.z, m4.w)));
        }
        if (cnt > 0)
            local += 0.5f * (dmin + dsum / (float)cnt) * g_m[cell >> 7];
    }
    red[tid] = local;
    __syncthreads();
    for (int s = 256; s > 0; s >>= 1) {
        if (tid < s) red[tid] += red[tid + s];
        __syncthreads();
    }
    if (tid == 0) out[0] = red[0] * (1.0f / (float)(NOBJ * NP));
}

// =================================================================
// kernel_launch: 5 launches, graph-capturable, no allocations,
// no static state.
// =================================================================
extern "C" void kernel_launch(void* const* d_in, const int* in_sizes, int n_in,
                              void* d_out, int out_size) {
    const float* ps1   = nullptr;
    const float* ps2   = nullptr;
    const float* feats = nullptr;
    const float* kp    = nullptr;
    for (int i = 0; i < n_in; i++) {
        if (in_sizes[i] == 37748736)      feats = (const float*)d_in[i];
        else if (in_sizes[i] == 65536)    ps2   = (const float*)d_in[i];
        else if (in_sizes[i] == 4096) {
            if (!ps1) ps1 = (const float*)d_in[i];
            else      kp  = (const float*)d_in[i];
        }
    }
    float* out = (float*)d_out;

    // Non-stream, idempotent; safe during graph capture.
    cudaFuncSetAttribute(gemm_mma_kernel,
                         cudaFuncAttributeMaxDynamicSharedMemorySize, GSM_TOTAL);

    m_kernel<<<NOBJ, 256>>>(ps2);
    transpose_kernel<<<dim3(HWd / 32, Cd / 32), dim3(8, 32)>>>(feats);
    sample_kernel<<<NPTS / 8, dim3(32, 8)>>>(kp, ps2);
    gemm_mma_kernel<<<dim3(NTILES, NOBJ), 256, GSM_TOTAL>>>(ps1, ps2);
    final_kernel<<<1, 512>>>(out);
}